// round 14
// baseline (speedup 1.0000x reference)
#include <cuda_runtime.h>
#include <cuda_fp16.h>
#include <math.h>
#include <stdint.h>

// Problem constants
#define BB 4
#define SS 1024
#define DD 1024
#define HH 16
#define HDD 64
#define EE 8
#define FF 4096
#define NTOK 4096      // B*S
#define NSLOT 8192     // NTOK * K(=2)
#define RMS_EPS 1e-6f
#define ATT_SCALE 0.125f   // 1/sqrt(64)

// ---------------- scratch (static device globals) ---------------------------
__device__ float g_xn[NTOK * DD];
__device__ float g_h[NTOK * DD];
__device__ float g_ypair[(size_t)NSLOT * DD];
__device__ float g_gate[NSLOT];
__device__ int   g_expcnt[EE];
__device__ int   g_expslots[EE * NTOK];
// fp16 operands
__device__ __half g_w1h[(size_t)EE * FF * DD];
__device__ __half g_w3h[(size_t)EE * FF * DD];
__device__ __half g_w2h[(size_t)EE * DD * FF];
__device__ __half g_wqh[DD * DD];
__device__ __half g_wkh[DD * DD];
__device__ __half g_wvh[DD * DD];
__device__ __half g_woh[DD * DD];
__device__ __half g_xnh[NTOK * DD];
__device__ __half g_qhh[NTOK * DD];   // q (fp16; rotated+scaled in place by rope)
__device__ __half g_khh[NTOK * DD];   // k (fp16; rotated in place by rope)
__device__ __half g_vhh[NTOK * DD];
__device__ __half g_atth[NTOK * DD];  // attention output (fp16)
__device__ __half g_hidh[(size_t)NSLOT * FF];

// ---------------- helpers ---------------------------------------------------
__device__ __forceinline__ void mma_f16(float* c, const uint32_t* a, const uint32_t* b) {
    asm volatile(
        "mma.sync.aligned.m16n8k16.row.col.f32.f16.f16.f32 "
        "{%0,%1,%2,%3}, {%4,%5,%6,%7}, {%8,%9}, {%0,%1,%2,%3};\n"
        : "+f"(c[0]), "+f"(c[1]), "+f"(c[2]), "+f"(c[3])
        : "r"(a[0]), "r"(a[1]), "r"(a[2]), "r"(a[3]), "r"(b[0]), "r"(b[1]));
}

__device__ __forceinline__ void cp16(uint32_t dst, const void* src) {
    asm volatile("cp.async.cg.shared.global [%0], [%1], 16;\n"
                 :: "r"(dst), "l"(src));
}
__device__ __forceinline__ void cp16z(uint32_t dst, const void* src, int ok) {
    asm volatile("cp.async.cg.shared.global [%0], [%1], 16, %2;\n"
                 :: "r"(dst), "l"(src), "r"(ok ? 16 : 0));
}
__device__ __forceinline__ void cp_commit() {
    asm volatile("cp.async.commit_group;\n" ::: "memory");
}
template <int N>
__device__ __forceinline__ void cp_wait() {
    asm volatile("cp.async.wait_group %0;\n" :: "n"(N) : "memory");
}

// ---- fp16 smem tiles: 32-k row = 16 words, stride 20 words ------------------
#define HSTR 20
#define HA_TILE (128 * HSTR)                  // 2560 words
#define HB_TILE (64 * HSTR)                   // 1280 words
#define W13H_STAGE (HA_TILE + 2 * HB_TILE)
#define W13H_SMEM  (2 * W13H_STAGE * 4)       // 40960 B
#define PROJH_STAGE (2 * HA_TILE)             // A(128) + B(128)
#define PROJH_SMEM  (2 * PROJH_STAGE * 4)     // 40960 B

// ---------------- fp32 -> fp16 conversion (4x float4 per thread) -------------
__global__ __launch_bounds__(256) void cvt_h4_kernel(
    const float4* __restrict__ src, __half2* __restrict__ dst)
{
    int i = (blockIdx.x * 256 + threadIdx.x) * 4;
    float4 a = src[i], b = src[i + 1], c = src[i + 2], d = src[i + 3];
    dst[2 * i + 0] = __floats2half2_rn(a.x, a.y);
    dst[2 * i + 1] = __floats2half2_rn(a.z, a.w);
    dst[2 * i + 2] = __floats2half2_rn(b.x, b.y);
    dst[2 * i + 3] = __floats2half2_rn(b.z, b.w);
    dst[2 * i + 4] = __floats2half2_rn(c.x, c.y);
    dst[2 * i + 5] = __floats2half2_rn(c.z, c.w);
    dst[2 * i + 6] = __floats2half2_rn(d.x, d.y);
    dst[2 * i + 7] = __floats2half2_rn(d.z, d.w);
}

// ---------------- RMSNorm (fp32 optional + fp16 out) -------------------------
__global__ __launch_bounds__(256) void rmsnorm_kernel(
    const float* __restrict__ x, const float* __restrict__ w,
    float* __restrict__ out, __half* __restrict__ outh)
{
    int t = blockIdx.x;
    const float4* xr = (const float4*)(x + (size_t)t * DD);
    float4 v = xr[threadIdx.x];
    float ss = v.x * v.x + v.y * v.y + v.z * v.z + v.w * v.w;
    #pragma unroll
    for (int o = 16; o; o >>= 1) ss += __shfl_xor_sync(0xffffffffu, ss, o);
    __shared__ float sh[8];
    __shared__ float stot;
    int warp = threadIdx.x >> 5;
    if ((threadIdx.x & 31) == 0) sh[warp] = ss;
    __syncthreads();
    if (threadIdx.x == 0) {
        float s = 0.f;
        #pragma unroll
        for (int i = 0; i < 8; i++) s += sh[i];
        stot = rsqrtf(s / (float)DD + RMS_EPS);
    }
    __syncthreads();
    float sc = stot;
    float4 wv = ((const float4*)w)[threadIdx.x];
    float4 o;
    o.x = v.x * sc * wv.x; o.y = v.y * sc * wv.y;
    o.z = v.z * sc * wv.z; o.w = v.w * sc * wv.w;
    if (out) ((float4*)(out + (size_t)t * DD))[threadIdx.x] = o;
    __half2* dh = (__half2*)(outh + (size_t)t * DD);
    dh[threadIdx.x * 2]     = __floats2half2_rn(o.x, o.y);
    dh[threadIdx.x * 2 + 1] = __floats2half2_rn(o.z, o.w);
}

// ---------------- dense fp16 GEMM core macros --------------------------------
#define ISSUE_PROJH(tile, st) do {                                             \
    const int ko_ = (tile) * 32;                                               \
    const uint32_t o_ = (uint32_t)(st) * PROJH_STAGE * 4;                      \
    cp16(dA0 + o_,      Ap + ko_);                                             \
    cp16(dA0 + o_ + 16, Ap + ko_ + 8);                                         \
    cp16(dB0 + o_,      Bp + ko_);                                             \
    cp16(dB0 + o_ + 16, Bp + ko_ + 8);                                         \
    cp_commit();                                                               \
} while (0)

#define COMPUTE_TILE_H(Ab, Bb)                                                 \
    _Pragma("unroll")                                                          \
    for (int s = 0; s < 2; s++) {                                              \
        int kb = s * 8;                                                        \
        uint32_t bf[4][2];                                                     \
        _Pragma("unroll")                                                      \
        for (int ni = 0; ni < 4; ni++) {                                       \
            int n = warpN * 32 + ni * 8 + g;                                   \
            bf[ni][0] = (Bb)[n * HSTR + kb + t];                               \
            bf[ni][1] = (Bb)[n * HSTR + kb + t + 4];                           \
        }                                                                      \
        _Pragma("unroll")                                                      \
        for (int mi = 0; mi < 4; mi++) {                                       \
            int m = warpM * 64 + mi * 16 + g;                                  \
            uint32_t af[4];                                                    \
            af[0] = (Ab)[m * HSTR + kb + t];                                   \
            af[1] = (Ab)[(m + 8) * HSTR + kb + t];                             \
            af[2] = (Ab)[m * HSTR + kb + t + 4];                               \
            af[3] = (Ab)[(m + 8) * HSTR + kb + t + 4];                         \
            _Pragma("unroll")                                                  \
            for (int ni = 0; ni < 4; ni++)                                     \
                mma_f16(acc[mi][ni], af, bf[ni]);                              \
        }                                                                      \
    }

// ---------------- fused QKV projection (fp16 mma, fp16 out) ------------------
__global__ __launch_bounds__(256) void gemm_qkv_h(
    const __half* __restrict__ A,
    __half* __restrict__ qo, __half* __restrict__ ko, __half* __restrict__ vo)
{
    extern __shared__ uint32_t smbuf[];
    const uint32_t smb = (uint32_t)__cvta_generic_to_shared(smbuf);
    const int tid = threadIdx.x;
    const int lane = tid & 31, warp = tid >> 5;
    const int warpM = warp >> 2, warpN = warp & 3;
    const int g = lane >> 2, t = lane & 3;
    const int m0 = blockIdx.y * 128;
    const int n0t = blockIdx.x * 128;

    const __half* W; __half* C; int n0;
    if (n0t < DD)            { W = g_wqh; C = qo; n0 = n0t; }
    else if (n0t < 2 * DD)   { W = g_wkh; C = ko; n0 = n0t - DD; }
    else                     { W = g_wvh; C = vo; n0 = n0t - 2 * DD; }

    float acc[4][4][4] = {};
    const int arow_f = tid >> 1;
    const int ac = (tid & 1) * 2;
    const __half* Ap = A + (size_t)(m0 + arow_f) * DD + ac * 8;
    const __half* Bp = W + (size_t)(n0 + arow_f) * DD + ac * 8;
    const uint32_t dA0 = smb + (arow_f * HSTR + ac * 4) * 4;
    const uint32_t dB0 = smb + HA_TILE * 4 + (arow_f * HSTR + ac * 4) * 4;

    const int nt = DD / 32;
    ISSUE_PROJH(0, 0);
    for (int kt = 0; kt < nt; kt++) {
        const int buf = kt & 1;
        if (kt + 1 < nt) { ISSUE_PROJH(kt + 1, buf ^ 1); cp_wait<1>(); }
        else             { cp_wait<0>(); }
        __syncthreads();
        const uint32_t* Sb = smbuf + buf * PROJH_STAGE;
        const uint32_t* Ab = Sb;
        const uint32_t* Bb = Sb + HA_TILE;
        COMPUTE_TILE_H(Ab, Bb);
        __syncthreads();
    }

    #pragma unroll
    for (int mi = 0; mi < 4; mi++) {
        int r0 = m0 + warpM * 64 + mi * 16 + g;
        #pragma unroll
        for (int ni = 0; ni < 4; ni++) {
            int c = n0 + warpN * 32 + ni * 8 + 2 * t;
            size_t i0 = (size_t)r0 * DD + c;
            size_t i1 = i0 + (size_t)8 * DD;
            *(__half2*)(C + i0) = __floats2half2_rn(acc[mi][ni][0], acc[mi][ni][1]);
            *(__half2*)(C + i1) = __floats2half2_rn(acc[mi][ni][2], acc[mi][ni][3]);
        }
    }
}

// ---------------- wo projection (fp16 mma, fp32 resid + out) -----------------
__global__ __launch_bounds__(256) void gemm_wo_h(
    const __half* __restrict__ A, const float* __restrict__ resid,
    float* __restrict__ C)
{
    extern __shared__ uint32_t smbuf[];
    const uint32_t smb = (uint32_t)__cvta_generic_to_shared(smbuf);
    const int tid = threadIdx.x;
    const int lane = tid & 31, warp = tid >> 5;
    const int warpM = warp >> 2, warpN = warp & 3;
    const int g = lane >> 2, t = lane & 3;
    const int m0 = blockIdx.y * 128, n0 = blockIdx.x * 128;

    float acc[4][4][4] = {};
    const int arow_f = tid >> 1;
    const int ac = (tid & 1) * 2;
    const __half* Ap = A + (size_t)(m0 + arow_f) * DD + ac * 8;
    const __half* Bp = g_woh + (size_t)(n0 + arow_f) * DD + ac * 8;
    const uint32_t dA0 = smb + (arow_f * HSTR + ac * 4) * 4;
    const uint32_t dB0 = smb + HA_TILE * 4 + (arow_f * HSTR + ac * 4) * 4;

    const int nt = DD / 32;
    ISSUE_PROJH(0, 0);
    for (int kt = 0; kt < nt; kt++) {
        const int buf = kt & 1;
        if (kt + 1 < nt) { ISSUE_PROJH(kt + 1, buf ^ 1); cp_wait<1>(); }
        else             { cp_wait<0>(); }
        __syncthreads();
        const uint32_t* Sb = smbuf + buf * PROJH_STAGE;
        const uint32_t* Ab = Sb;
        const uint32_t* Bb = Sb + HA_TILE;
        COMPUTE_TILE_H(Ab, Bb);
        __syncthreads();
    }

    #pragma unroll
    for (int mi = 0; mi < 4; mi++) {
        int r0 = m0 + warpM * 64 + mi * 16 + g;
        #pragma unroll
        for (int ni = 0; ni < 4; ni++) {
            int c = n0 + warpN * 32 + ni * 8 + 2 * t;
            size_t i0 = (size_t)r0 * DD + c;
            size_t i1 = i0 + (size_t)8 * DD;
            float2 r = *(const float2*)(resid + i0);
            *(float2*)(C + i0) = make_float2(acc[mi][ni][0] + r.x,
                                             acc[mi][ni][1] + r.y);
            r = *(const float2*)(resid + i1);
            *(float2*)(C + i1) = make_float2(acc[mi][ni][2] + r.x,
                                             acc[mi][ni][3] + r.y);
        }
    }
}

// ---------------- RoPE: fp16 in-place (q pre-scaled) -------------------------
__global__ void rope_h16_kernel(__half* __restrict__ qh, __half* __restrict__ kh,
                                const float* __restrict__ cosb,
                                const float* __restrict__ sinb)
{
    int idx = blockIdx.x * blockDim.x + threadIdx.x;
    int i = idx & 31;
    int th = idx >> 5;
    int t = th >> 4;
    int s = t & (SS - 1);
    float c = cosb[s * 32 + i], sn = sinb[s * 32 + i];
    size_t pi = ((size_t)th * HDD + i * 2) >> 1;
    __half2 qv = ((__half2*)qh)[pi];
    float xr = __low2float(qv), xi = __high2float(qv);
    ((__half2*)qh)[pi] = __floats2half2_rn((xr * c - xi * sn) * ATT_SCALE,
                                           (xr * sn + xi * c) * ATT_SCALE);
    __half2 kv = ((__half2*)kh)[pi];
    xr = __low2float(kv); xi = __high2float(kv);
    ((__half2*)kh)[pi] = __floats2half2_rn(xr * c - xi * sn, xr * sn + xi * c);
}

// ---------------- Flash attention (fp16 mma, fp32 softmax) -------------------
#define ASTRH 36
#define ATTH_SMEM (4 * 64 * ASTRH * 4)   // 36864 B
__global__ __launch_bounds__(128) void attn_h_kernel(
    const __half* __restrict__ Q, const __half* __restrict__ K,
    const __half* __restrict__ V, __half* __restrict__ O,
    const int* __restrict__ causal_flag)
{
    extern __shared__ uint32_t smw[];
    uint32_t* Qs = smw;
    uint32_t* Ks = Qs + 64 * ASTRH;
    uint32_t* Vt = Ks + 64 * ASTRH;   // transposed halves: [d][kpos]
    uint32_t* Ps = Vt + 64 * ASTRH;
    __half* Vth = (__half*)Vt;
    const int qt = blockIdx.x, bh = blockIdx.y;
    const int b = bh >> 4, h = bh & 15;
    const int tid = threadIdx.x;
    const int warp = tid >> 5, lane = tid & 31;
    const int g = lane >> 2, t = lane & 3;
    const int causal = *causal_flag;
    const size_t base = (size_t)b * SS * DD + (size_t)h * HDD;
    const __half* Qb = Q + base;
    const __half* Kb = K + base;
    const __half* Vb = V + base;
    const int q0 = qt * 64;

    {   // load Q tile (fp16, already scaled)
        int row = tid >> 1;
        int cw = (tid & 1) * 16;
        const uint4* src = (const uint4*)(Qb + (size_t)(q0 + row) * DD + cw * 2);
        #pragma unroll
        for (int j = 0; j < 4; j++)
            *(uint4*)&Qs[row * ASTRH + cw + j * 4] = src[j];
    }

    float m_run0 = -1e30f, m_run1 = -1e30f;
    float l_run0 = 0.f, l_run1 = 0.f;
    float Oacc[8][4] = {};
    const int mrow = warp * 16 + g;

    const int ktmax = causal ? qt : (SS / 64 - 1);
    for (int kt = 0; kt <= ktmax; kt++) {
        __syncthreads();
        {   // load K tile + transposed V tile
            int row = tid >> 1;
            int cw = (tid & 1) * 16;
            const uint4* ks = (const uint4*)(Kb + (size_t)(kt * 64 + row) * DD + cw * 2);
            #pragma unroll
            for (int j = 0; j < 4; j++)
                *(uint4*)&Ks[row * ASTRH + cw + j * 4] = ks[j];
            const __half2* vs = (const __half2*)(Vb + (size_t)(kt * 64 + row) * DD + cw * 2);
            #pragma unroll
            for (int j = 0; j < 16; j++) {
                __half2 p = vs[j];
                int c = cw * 2 + j * 2;
                Vth[(c + 0) * (ASTRH * 2) + row] = __low2half(p);
                Vth[(c + 1) * (ASTRH * 2) + row] = __high2half(p);
            }
        }
        __syncthreads();

        // S = Q @ K^T
        float sacc[8][4] = {};
        #pragma unroll
        for (int s = 0; s < 4; s++) {
            int kb = s * 8;
            uint32_t af[4];
            af[0] = Qs[mrow * ASTRH + kb + t];
            af[1] = Qs[(mrow + 8) * ASTRH + kb + t];
            af[2] = Qs[mrow * ASTRH + kb + t + 4];
            af[3] = Qs[(mrow + 8) * ASTRH + kb + t + 4];
            #pragma unroll
            for (int ni = 0; ni < 8; ni++) {
                uint32_t bf[2];
                bf[0] = Ks[(ni * 8 + g) * ASTRH + kb + t];
                bf[1] = Ks[(ni * 8 + g) * ASTRH + kb + t + 4];
                mma_f16(sacc[ni], af, bf);
            }
        }

        const int row0 = q0 + mrow, row1 = row0 + 8;
        if (causal && kt == qt) {
            #pragma unroll
            for (int ni = 0; ni < 8; ni++) {
                int c0 = kt * 64 + ni * 8 + 2 * t;
                if (c0     > row0) sacc[ni][0] = -1e30f;
                if (c0 + 1 > row0) sacc[ni][1] = -1e30f;
                if (c0     > row1) sacc[ni][2] = -1e30f;
                if (c0 + 1 > row1) sacc[ni][3] = -1e30f;
            }
        }

        float ml0 = -1e30f, ml1 = -1e30f;
        #pragma unroll
        for (int ni = 0; ni < 8; ni++) {
            ml0 = fmaxf(ml0, fmaxf(sacc[ni][0], sacc[ni][1]));
            ml1 = fmaxf(ml1, fmaxf(sacc[ni][2], sacc[ni][3]));
        }
        ml0 = fmaxf(ml0, __shfl_xor_sync(0xffffffffu, ml0, 1));
        ml0 = fmaxf(ml0, __shfl_xor_sync(0xffffffffu, ml0, 2));
        ml1 = fmaxf(ml1, __shfl_xor_sync(0xffffffffu, ml1, 1));
        ml1 = fmaxf(ml1, __shfl_xor_sync(0xffffffffu, ml1, 2));
        float mn0 = fmaxf(m_run0, ml0), mn1 = fmaxf(m_run1, ml1);
        float a0 = expf(m_run0 - mn0), a1 = expf(m_run1 - mn1);
        float ps0 = 0.f, ps1 = 0.f;
        #pragma unroll
        for (int ni = 0; ni < 8; ni++) {
            float p0 = expf(sacc[ni][0] - mn0);
            float p1 = expf(sacc[ni][1] - mn0);
            float p2 = expf(sacc[ni][2] - mn1);
            float p3 = expf(sacc[ni][3] - mn1);
            ps0 += p0 + p1; ps1 += p2 + p3;
            __half2 hp0 = __floats2half2_rn(p0, p1);
            __half2 hp1 = __floats2half2_rn(p2, p3);
            Ps[mrow * ASTRH + ni * 4 + t]       = *(uint32_t*)&hp0;
            Ps[(mrow + 8) * ASTRH + ni * 4 + t] = *(uint32_t*)&hp1;
        }
        ps0 += __shfl_xor_sync(0xffffffffu, ps0, 1);
        ps0 += __shfl_xor_sync(0xffffffffu, ps0, 2);
        ps1 += __shfl_xor_sync(0xffffffffu, ps1, 1);
        ps1 += __shfl_xor_sync(0xffffffffu, ps1, 2);
        l_run0 = l_run0 * a0 + ps0;
        l_run1 = l_run1 * a1 + ps1;
        m_run0 = mn0; m_run1 = mn1;
        #pragma unroll
        for (int ni = 0; ni < 8; ni++) {
            Oacc[ni][0] *= a0; Oacc[ni][1] *= a0;
            Oacc[ni][2] *= a1; Oacc[ni][3] *= a1;
        }
        __syncwarp();

        // O += P @ V
        #pragma unroll
        for (int s = 0; s < 4; s++) {
            int kb = s * 8;
            uint32_t af[4];
            af[0] = Ps[mrow * ASTRH + kb + t];
            af[1] = Ps[(mrow + 8) * ASTRH + kb + t];
            af[2] = Ps[mrow * ASTRH + kb + t + 4];
            af[3] = Ps[(mrow + 8) * ASTRH + kb + t + 4];
            #pragma unroll
            for (int ni = 0; ni < 8; ni++) {
                uint32_t bf[2];
                bf[0] = Vt[(ni * 8 + g) * ASTRH + kb + t];
                bf[1] = Vt[(ni * 8 + g) * ASTRH + kb + t + 4];
                mma_f16(Oacc[ni], af, bf);
            }
        }
    }

    float i0 = 1.f / l_run0, i1 = 1.f / l_run1;
    const int row0 = q0 + mrow;
    __half* dst0 = O + (size_t)(b * SS + row0) * DD + (size_t)h * HDD;
    __half* dst1 = dst0 + (size_t)8 * DD;
    #pragma unroll
    for (int ni = 0; ni < 8; ni++) {
        int d = ni * 8 + 2 * t;
        *(__half2*)(dst0 + d) = __floats2half2_rn(Oacc[ni][0] * i0, Oacc[ni][1] * i0);
        *(__half2*)(dst1 + d) = __floats2half2_rn(Oacc[ni][2] * i1, Oacc[ni][3] * i1);
    }
}

// ---------------- fused w1+w3 expert GEMM (fp16 mma) -------------------------
__global__ __launch_bounds__(256) void moe_w13_h(const __half* __restrict__ A)
{
    const int e = blockIdx.z;
    const int count = g_expcnt[e];
    const int m0 = blockIdx.y * 128;
    if (m0 >= count) return;

    extern __shared__ uint32_t smbuf[];
    __shared__ int srow[128];
    const uint32_t smb = (uint32_t)__cvta_generic_to_shared(smbuf);

    const int tid = threadIdx.x;
    if (tid < 128) {
        int r = m0 + tid;
        srow[tid] = (r < count) ? g_expslots[e * NTOK + r] : -1;
    }
    __syncthreads();

    const int lane = tid & 31, warp = tid >> 5;
    const int warpM = warp >> 2, warpN = warp & 3;
    const int g = lane >> 2, t = lane & 3;
    const int n0 = blockIdx.x * 64;
    float acc1[4][2][4] = {};
    float acc3[4][2][4] = {};

    const int arow_f = tid >> 1;
    const int ac = (tid & 1) * 2;
    const int s_a = srow[arow_f];
    const int aok = (s_a >= 0);
    const __half* aptr = A + (size_t)(aok ? (s_a >> 1) : 0) * DD + ac * 8;
    const int brow = (tid & 127) >> 1;
    const int bc = (tid & 1) * 2;
    const __half* bptr = ((tid < 128) ? g_w1h : g_w3h)
                         + (size_t)e * FF * DD + (size_t)(n0 + brow) * DD + bc * 8;
    const uint32_t bRegion = (tid < 128) ? (HA_TILE * 4) : ((HA_TILE + HB_TILE) * 4);
    const uint32_t dA0 = smb + (arow_f * HSTR + ac * 4) * 4;
    const uint32_t dB0 = smb + bRegion + (brow * HSTR + bc * 4) * 4;

#define ISSUE_W13H(tile, st) do {                                              \
    const int ko_ = (tile) * 32;                                               \
    const uint32_t o_ = (uint32_t)(st) * W13H_STAGE * 4;                       \
    cp16z(dA0 + o_,      aptr + ko_,     aok);                                 \
    cp16z(dA0 + o_ + 16, aptr + ko_ + 8, aok);                                 \
    cp16 (dB0 + o_,      bptr + ko_);                                          \
    cp16 (dB0 + o_ + 16, bptr + ko_ + 8);                                      \
    cp_commit();                                                               \
} while (0)

    const int nt = DD / 32;
    ISSUE_W13H(0, 0);
    for (int kt = 0; kt < nt; kt++) {
        const int buf = kt & 1;
        if (kt + 1 < nt) { ISSUE_W13H(kt + 1, buf ^ 1); cp_wait<1>(); }
        else             { cp_wait<0>(); }
        __syncthreads();

        const uint32_t* Sb  = smbuf + buf * W13H_STAGE;
        const uint32_t* Ab  = Sb;
        const uint32_t* B1b = Sb + HA_TILE;
        const uint32_t* B3b = Sb + HA_TILE + HB_TILE;
        #pragma unroll
        for (int s = 0; s < 2; s++) {
            int kb = s * 8;
            uint32_t bf1[2][2], bf3[2][2];
            #pragma unroll
            for (int ni = 0; ni < 2; ni++) {
                int n = warpN * 16 + ni * 8 + g;
                bf1[ni][0] = B1b[n * HSTR + kb + t];
                bf1[ni][1] = B1b[n * HSTR + kb + t + 4];
                bf3[ni][0] = B3b[n * HSTR + kb + t];
                bf3[ni][1] = B3b[n * HSTR + kb + t + 4];
            }
            #pragma unroll
            for (int mi = 0; mi < 4; mi++) {
                int m = warpM * 64 + mi * 16 + g;
                uint32_t af[4];
                af[0] = Ab[m * HSTR + kb + t];
                af[1] = Ab[(m + 8) * HSTR + kb + t];
                af[2] = Ab[m * HSTR + kb + t + 4];
                af[3] = Ab[(m + 8) * HSTR + kb + t + 4];
                #pragma unroll
                for (int ni = 0; ni < 2; ni++) {
                    mma_f16(acc1[mi][ni], af, bf1[ni]);
                    mma_f16(acc3[mi][ni], af, bf3[ni]);
                }
            }
        }
        __syncthreads();
    }

    #pragma unroll
    for (int mi = 0; mi < 4; mi++) {
        int mloc0 = warpM * 64 + mi * 16 + g;
        #pragma unroll
        for (int half = 0; half < 2; half++) {
            int mloc = mloc0 + half * 8;
            int s = srow[mloc];
            if (s < 0) continue;
            #pragma unroll
            for (int ni = 0; ni < 2; ni++) {
                int c = n0 + warpN * 16 + ni * 8 + 2 * t;
                float h1x = acc1[mi][ni][half * 2],     h1y = acc1[mi][ni][half * 2 + 1];
                float h3x = acc3[mi][ni][half * 2],     h3y = acc3[mi][ni][half * 2 + 1];
                float ox = (h1x / (1.f + expf(-h1x))) * h3x;
                float oy = (h1y / (1.f + expf(-h1y))) * h3y;
                *(__half2*)(&g_hidh[(size_t)s * FF + c]) = __floats2half2_rn(ox, oy);
            }
        }
    }
}

// ---------------- w2 expert GEMM (fp16 mma, N=128) ---------------------------
__global__ __launch_bounds__(256) void moe_w2_h()
{
    const int e = blockIdx.z;
    const int count = g_expcnt[e];
    const int m0 = blockIdx.y * 128;
    if (m0 >= count) return;

    extern __shared__ uint32_t smbuf[];
    __shared__ int srow[128];
    const uint32_t smb = (uint32_t)__cvta_generic_to_shared(smbuf);

    const int tid = threadIdx.x;
    if (tid < 128) {
        int r = m0 + tid;
        srow[tid] = (r < count) ? g_expslots[e * NTOK + r] : -1;
    }
    __syncthreads();

    const int lane = tid & 31, warp = tid >> 5;
    const int warpM = warp >> 2, warpN = warp & 3;
    const int g = lane >> 2, t = lane & 3;
    const int n0 = blockIdx.x * 128;
    float acc[4][4][4] = {};

    const int arow_f = tid >> 1;
    const int ac = (tid & 1) * 2;
    const int s_a = srow[arow_f];
    const int aok = (s_a >= 0);
    const __half* aptr = g_hidh + (size_t)(aok ? s_a : 0) * FF + ac * 8;
    const __half* bptr = g_w2h + (size_t)e * DD * FF
                         + (size_t)(n0 + arow_f) * FF + ac * 8;
    const uint32_t dA0 = smb + (arow_f * HSTR + ac * 4) * 4;
    const uint32_t dB0 = smb + HA_TILE * 4 + (arow_f * HSTR + ac * 4) * 4;

#define ISSUE_W2H(tile, st) do {                                               \
    const int ko_ = (tile) * 32;                                               \
    const uint32_t o_ = (uint32_t)(st) * PROJH_STAGE * 4;                      \
    cp16z(dA0 + o_,      aptr + ko_,     aok);                                 \
    cp16z(dA0 + o_ + 16, aptr + ko_ + 8, aok);                                 \
    cp16 (dB0 + o_,      bptr + ko_);                                          \
    cp16 (dB0 + o_ + 16, bptr + ko_ + 8);                                      \
    cp_commit();                                                               \
} while (0)

    const int nt = FF / 32;
    ISSUE_W2H(0, 0);
    for (int kt = 0; kt < nt; kt++) {
        const int buf = kt & 1;
        if (kt + 1 < nt) { ISSUE_W2H(kt + 1, buf ^ 1); cp_wait<1>(); }
        else             { cp_wait<0>(); }
        __syncthreads();

        const uint32_t* Sb = smbuf + buf * PROJH_STAGE;
        const uint32_t* Ab = Sb;
        const uint32_t* Bb = Sb + HA_TILE;
        COMPUTE_TILE_H(Ab, Bb);
        __syncthreads();
    }

    #pragma unroll
    for (int mi = 0; mi < 4; mi++) {
        int mloc0 = warpM * 64 + mi * 16 + g;
        #pragma unroll
        for (int half = 0; half < 2; half++) {
            int mloc = mloc0 + half * 8;
            int s = srow[mloc];
            if (s < 0) continue;
            #pragma unroll
            for (int ni = 0; ni < 4; ni++) {
                int c = n0 + warpN * 32 + ni * 8 + 2 * t;
                *(float2*)(&g_ypair[(size_t)s * DD + c]) =
                    make_float2(acc[mi][ni][half * 2], acc[mi][ni][half * 2 + 1]);
            }
        }
    }
}

// ---------------- router + top-2 ---------------------------------------------
__global__ void zero_counts_kernel()
{
    if (threadIdx.x < EE) g_expcnt[threadIdx.x] = 0;
}

__global__ __launch_bounds__(256) void router_kernel(
    const float* __restrict__ xn, const float* __restrict__ rw,
    const float* __restrict__ rb)
{
    int t = blockIdx.x;
    float4 xv = ((const float4*)(xn + (size_t)t * DD))[threadIdx.x];
    float lg[EE];
    #pragma unroll
    for (int e = 0; e < EE; e++) {
        float4 wv = ((const float4*)(rw + (size_t)e * DD))[threadIdx.x];
        lg[e] = xv.x * wv.x + xv.y * wv.y + xv.z * wv.z + xv.w * wv.w;
    }
    #pragma unroll
    for (int o = 16; o; o >>= 1)
        #pragma unroll
        for (int e = 0; e < EE; e++)
            lg[e] += __shfl_xor_sync(0xffffffffu, lg[e], o);
    __shared__ float sh[EE][8];
    int warp = threadIdx.x >> 5;
    if ((threadIdx.x & 31) == 0)
        #pragma unroll
        for (int e = 0; e < EE; e++) sh[e][warp] = lg[e];
    __syncthreads();
    if (threadIdx.x == 0) {
        float logits[EE];
        #pragma unroll
        for (int e = 0; e < EE; e++) {
            float s = rb[e];
            #pragma unroll
            for (int w = 0; w < 8; w++) s += sh[e][w];
            logits[e] = s;
        }
        int i0 = 0;
        #pragma unroll
        for (int e = 1; e < EE; e++) if (logits[e] > logits[i0]) i0 = e;
        int i1 = -1;
        #pragma unroll
        for (int e = 0; e < EE; e++)
            if (e != i0 && (i1 < 0 || logits[e] > logits[i1])) i1 = e;
        float ex = expf(logits[i1] - logits[i0]);
        float denom = 1.f + ex;
        float p0 = 1.f / denom, p1 = ex / denom;
        int s0 = atomicAdd(&g_expcnt[i0], 1);
        g_expslots[i0 * NTOK + s0] = 2 * t;
        g_gate[2 * t] = p0;
        int s1 = atomicAdd(&g_expcnt[i1], 1);
        g_expslots[i1 * NTOK + s1] = 2 * t + 1;
        g_gate[2 * t + 1] = p1;
    }
}

// ---------------- final combine ----------------------------------------------
__global__ __launch_bounds__(256) void combine_kernel(float* __restrict__ out)
{
    int idx = blockIdx.x * 256 + threadIdx.x;
    int t = idx >> 8;
    int col = idx & 255;
    float g0 = g_gate[2 * t], g1 = g_gate[2 * t + 1];
    float4 hv = ((const float4*)g_h)[idx];
    float4 y0 = ((const float4*)g_ypair)[(size_t)(2 * t) * 256 + col];
    float4 y1 = ((const float4*)g_ypair)[(size_t)(2 * t + 1) * 256 + col];
    float4 o;
    o.x = hv.x + g0 * y0.x + g1 * y1.x;
    o.y = hv.y + g0 * y0.y + g1 * y1.y;
    o.z = hv.z + g0 * y0.z + g1 * y1.z;
    o.w = hv.w + g0 * y0.w + g1 * y1.w;
    ((float4*)out)[idx] = o;
}

// ---------------- launch -----------------------------------------------------
extern "C" void kernel_launch(void* const* d_in, const int* in_sizes, int n_in,
                              void* d_out, int out_size)
{
    const float* q     = (const float*)d_in[0];
    const float* fcos  = (const float*)d_in[3];
    const float* fsin  = (const float*)d_in[4];
    const float* att_w = (const float*)d_in[5];
    const float* ffn_w = (const float*)d_in[6];
    const float* wq    = (const float*)d_in[7];
    const float* wk    = (const float*)d_in[8];
    const float* wv    = (const float*)d_in[9];
    const float* wo    = (const float*)d_in[10];
    const float* rw    = (const float*)d_in[11];
    const float* rb    = (const float*)d_in[12];
    const float* w1    = (const float*)d_in[13];
    const float* w2    = (const float*)d_in[14];
    const float* w3    = (const float*)d_in[15];
    const int*   causal= (const int*)d_in[16];
    float* out = (float*)d_out;

    float *p_xn, *p_h;
    __half *p_w1h, *p_w3h, *p_w2h, *p_xnh;
    __half *p_wqh, *p_wkh, *p_wvh, *p_woh;
    __half *p_qhh, *p_khh, *p_vhh, *p_atth;
    cudaGetSymbolAddress((void**)&p_xn, g_xn);
    cudaGetSymbolAddress((void**)&p_h, g_h);
    cudaGetSymbolAddress((void**)&p_w1h, g_w1h);
    cudaGetSymbolAddress((void**)&p_w3h, g_w3h);
    cudaGetSymbolAddress((void**)&p_w2h, g_w2h);
    cudaGetSymbolAddress((void**)&p_xnh, g_xnh);
    cudaGetSymbolAddress((void**)&p_wqh, g_wqh);
    cudaGetSymbolAddress((void**)&p_wkh, g_wkh);
    cudaGetSymbolAddress((void**)&p_wvh, g_wvh);
    cudaGetSymbolAddress((void**)&p_woh, g_woh);
    cudaGetSymbolAddress((void**)&p_qhh, g_qhh);
    cudaGetSymbolAddress((void**)&p_khh, g_khh);
    cudaGetSymbolAddress((void**)&p_vhh, g_vhh);
    cudaGetSymbolAddress((void**)&p_atth, g_atth);

    cudaFuncSetAttribute(attn_h_kernel,
                         cudaFuncAttributeMaxDynamicSharedMemorySize, ATTH_SMEM);
    cudaFuncSetAttribute(gemm_qkv_h,
                         cudaFuncAttributeMaxDynamicSharedMemorySize, PROJH_SMEM);
    cudaFuncSetAttribute(gemm_wo_h,
                         cudaFuncAttributeMaxDynamicSharedMemorySize, PROJH_SMEM);
    cudaFuncSetAttribute(moe_w13_h,
                         cudaFuncAttributeMaxDynamicSharedMemorySize, W13H_SMEM);
    cudaFuncSetAttribute(moe_w2_h,
                         cudaFuncAttributeMaxDynamicSharedMemorySize, PROJH_SMEM);

    // 0. weight conversions to fp16 (4x float4 per thread)
    const int nWB = (EE * FF * DD / 16) / 256;   // 8192 blocks
    cvt_h4_kernel<<<nWB, 256>>>((const float4*)w1, (__half2*)p_w1h);
    cvt_h4_kernel<<<nWB, 256>>>((const float4*)w3, (__half2*)p_w3h);
    cvt_h4_kernel<<<nWB, 256>>>((const float4*)w2, (__half2*)p_w2h);
    const int nDB = (DD * DD / 16) / 256;        // 256 blocks
    cvt_h4_kernel<<<nDB, 256>>>((const float4*)wq, (__half2*)p_wqh);
    cvt_h4_kernel<<<nDB, 256>>>((const float4*)wk, (__half2*)p_wkh);
    cvt_h4_kernel<<<nDB, 256>>>((const float4*)wv, (__half2*)p_wvh);
    cvt_h4_kernel<<<nDB, 256>>>((const float4*)wo, (__half2*)p_woh);

    // 1. qn = rmsnorm(q) -> fp16
    rmsnorm_kernel<<<NTOK, 256>>>(q, att_w, (float*)nullptr, p_xnh);

    // 2. fused QKV projection (fp16 mma, fp16 out)
    gemm_qkv_h<<<dim3(3 * DD / 128, NTOK / 128), 256, PROJH_SMEM>>>(
        p_xnh, p_qhh, p_khh, p_vhh);

    // 3. RoPE in place on fp16 q/k (q pre-scaled)
    rope_h16_kernel<<<(NTOK * HH * (HDD / 2)) / 256, 256>>>(
        p_qhh, p_khh, fcos, fsin);

    // 4. flash attention (fp16 mma) -> fp16 out
    attn_h_kernel<<<dim3(SS / 64, BB * HH), 128, ATTH_SMEM>>>(
        p_qhh, p_khh, p_vhh, p_atth, causal);

    // 5. h = q + att @ wo^T
    gemm_wo_h<<<dim3(DD / 128, NTOK / 128), 256, PROJH_SMEM>>>(
        p_atth, q, p_h);

    // 6. hn = rmsnorm(h)
    rmsnorm_kernel<<<NTOK, 256>>>(p_h, ffn_w, p_xn, p_xnh);

    // 7. routing
    zero_counts_kernel<<<1, 32>>>();
    router_kernel<<<NTOK, 256>>>(p_xn, rw, rb);

    // 8. MoE (fp16 mma)
    moe_w13_h<<<dim3(FF / 64, NTOK / 128, EE), 256, W13H_SMEM>>>(p_xnh);
    moe_w2_h<<<dim3(DD / 128, NTOK / 128, EE), 256, PROJH_SMEM>>>();

    // 9. combine
    combine_kernel<<<NTOK, 256>>>(out);
}

// round 15
// speedup vs baseline: 1.0777x; 1.0777x over previous
#include <cuda_runtime.h>
#include <cuda_fp16.h>
#include <math.h>
#include <stdint.h>

// Problem constants
#define BB 4
#define SS 1024
#define DD 1024
#define HH 16
#define HDD 64
#define EE 8
#define FF 4096
#define NTOK 4096      // B*S
#define NSLOT 8192     // NTOK * K(=2)
#define RMS_EPS 1e-6f
#define ATT_SCALE 0.125f   // 1/sqrt(64)

// ---------------- scratch (static device globals) ---------------------------
__device__ float g_xn[NTOK * DD];
__device__ float g_h[NTOK * DD];
__device__ float g_ypair[(size_t)NSLOT * DD];
__device__ float g_gate[NSLOT];
__device__ int   g_expcnt[EE];
__device__ int   g_expslots[EE * NTOK];
// fp16 operands
__device__ __half g_w1h[(size_t)EE * FF * DD];
__device__ __half g_w3h[(size_t)EE * FF * DD];
__device__ __half g_w2h[(size_t)EE * DD * FF];
__device__ __half g_wqh[DD * DD];
__device__ __half g_wkh[DD * DD];
__device__ __half g_wvh[DD * DD];
__device__ __half g_woh[DD * DD];
__device__ __half g_xnh[NTOK * DD];
__device__ __half g_qhh[NTOK * DD];   // q (fp16; rotated+scaled in place by rope)
__device__ __half g_khh[NTOK * DD];   // k (fp16; rotated in place by rope)
__device__ __half g_vhh[NTOK * DD];
__device__ __half g_atth[NTOK * DD];  // attention output (fp16)
__device__ __half g_hidh[(size_t)NSLOT * FF];

// ---------------- helpers ---------------------------------------------------
__device__ __forceinline__ void mma_f16(float* c, const uint32_t* a, const uint32_t* b) {
    asm volatile(
        "mma.sync.aligned.m16n8k16.row.col.f32.f16.f16.f32 "
        "{%0,%1,%2,%3}, {%4,%5,%6,%7}, {%8,%9}, {%0,%1,%2,%3};\n"
        : "+f"(c[0]), "+f"(c[1]), "+f"(c[2]), "+f"(c[3])
        : "r"(a[0]), "r"(a[1]), "r"(a[2]), "r"(a[3]), "r"(b[0]), "r"(b[1]));
}

__device__ __forceinline__ void cp16(uint32_t dst, const void* src) {
    asm volatile("cp.async.cg.shared.global [%0], [%1], 16;\n"
                 :: "r"(dst), "l"(src));
}
__device__ __forceinline__ void cp16z(uint32_t dst, const void* src, int ok) {
    asm volatile("cp.async.cg.shared.global [%0], [%1], 16, %2;\n"
                 :: "r"(dst), "l"(src), "r"(ok ? 16 : 0));
}
__device__ __forceinline__ void cp_commit() {
    asm volatile("cp.async.commit_group;\n" ::: "memory");
}
template <int N>
__device__ __forceinline__ void cp_wait() {
    asm volatile("cp.async.wait_group %0;\n" :: "n"(N) : "memory");
}

// ---- fp16 smem tiles: 32-k row = 16 words, stride 20 words ------------------
#define HSTR 20
#define HA_TILE (128 * HSTR)                  // 2560 words
#define HB_TILE (64 * HSTR)                   // 1280 words
#define W13H_STAGE (HA_TILE + 2 * HB_TILE)
#define W13H_SMEM  (2 * W13H_STAGE * 4)       // 40960 B
#define PROJH_STAGE (2 * HA_TILE)             // A(128) + B(128)
#define PROJH_SMEM  (2 * PROJH_STAGE * 4)     // 40960 B

// ---------------- fp32 -> fp16 conversion (coalesced, MLP=4) -----------------
// Block owns a contiguous span of 1024 float4; thread handles tid + k*256.
__global__ __launch_bounds__(256) void cvt_h4c_kernel(
    const float4* __restrict__ src, __half2* __restrict__ dst)
{
    int base = blockIdx.x * 1024 + threadIdx.x;
    #pragma unroll
    for (int k = 0; k < 4; k++) {
        int i = base + k * 256;
        float4 v = src[i];
        dst[2 * i]     = __floats2half2_rn(v.x, v.y);
        dst[2 * i + 1] = __floats2half2_rn(v.z, v.w);
    }
}

// ---------------- RMSNorm (fp32 optional + fp16 out) -------------------------
__global__ __launch_bounds__(256) void rmsnorm_kernel(
    const float* __restrict__ x, const float* __restrict__ w,
    float* __restrict__ out, __half* __restrict__ outh)
{
    int t = blockIdx.x;
    const float4* xr = (const float4*)(x + (size_t)t * DD);
    float4 v = xr[threadIdx.x];
    float ss = v.x * v.x + v.y * v.y + v.z * v.z + v.w * v.w;
    #pragma unroll
    for (int o = 16; o; o >>= 1) ss += __shfl_xor_sync(0xffffffffu, ss, o);
    __shared__ float sh[8];
    __shared__ float stot;
    int warp = threadIdx.x >> 5;
    if ((threadIdx.x & 31) == 0) sh[warp] = ss;
    __syncthreads();
    if (threadIdx.x == 0) {
        float s = 0.f;
        #pragma unroll
        for (int i = 0; i < 8; i++) s += sh[i];
        stot = rsqrtf(s / (float)DD + RMS_EPS);
    }
    __syncthreads();
    float sc = stot;
    float4 wv = ((const float4*)w)[threadIdx.x];
    float4 o;
    o.x = v.x * sc * wv.x; o.y = v.y * sc * wv.y;
    o.z = v.z * sc * wv.z; o.w = v.w * sc * wv.w;
    if (out) ((float4*)(out + (size_t)t * DD))[threadIdx.x] = o;
    __half2* dh = (__half2*)(outh + (size_t)t * DD);
    dh[threadIdx.x * 2]     = __floats2half2_rn(o.x, o.y);
    dh[threadIdx.x * 2 + 1] = __floats2half2_rn(o.z, o.w);
}

// ---------------- dense fp16 GEMM core macros --------------------------------
#define ISSUE_PROJH(tile, st) do {                                             \
    const int ko_ = (tile) * 32;                                               \
    const uint32_t o_ = (uint32_t)(st) * PROJH_STAGE * 4;                      \
    cp16(dA0 + o_,      Ap + ko_);                                             \
    cp16(dA0 + o_ + 16, Ap + ko_ + 8);                                         \
    cp16(dB0 + o_,      Bp + ko_);                                             \
    cp16(dB0 + o_ + 16, Bp + ko_ + 8);                                         \
    cp_commit();                                                               \
} while (0)

#define COMPUTE_TILE_H(Ab, Bb)                                                 \
    _Pragma("unroll")                                                          \
    for (int s = 0; s < 2; s++) {                                              \
        int kb = s * 8;                                                        \
        uint32_t bf[4][2];                                                     \
        _Pragma("unroll")                                                      \
        for (int ni = 0; ni < 4; ni++) {                                       \
            int n = warpN * 32 + ni * 8 + g;                                   \
            bf[ni][0] = (Bb)[n * HSTR + kb + t];                               \
            bf[ni][1] = (Bb)[n * HSTR + kb + t + 4];                           \
        }                                                                      \
        _Pragma("unroll")                                                      \
        for (int mi = 0; mi < 4; mi++) {                                       \
            int m = warpM * 64 + mi * 16 + g;                                  \
            uint32_t af[4];                                                    \
            af[0] = (Ab)[m * HSTR + kb + t];                                   \
            af[1] = (Ab)[(m + 8) * HSTR + kb + t];                             \
            af[2] = (Ab)[m * HSTR + kb + t + 4];                               \
            af[3] = (Ab)[(m + 8) * HSTR + kb + t + 4];                         \
            _Pragma("unroll")                                                  \
            for (int ni = 0; ni < 4; ni++)                                     \
                mma_f16(acc[mi][ni], af, bf[ni]);                              \
        }                                                                      \
    }

// ---------------- fused QKV projection (fp16 mma, fp16 out) ------------------
__global__ __launch_bounds__(256) void gemm_qkv_h(
    const __half* __restrict__ A,
    __half* __restrict__ qo, __half* __restrict__ ko, __half* __restrict__ vo)
{
    extern __shared__ uint32_t smbuf[];
    const uint32_t smb = (uint32_t)__cvta_generic_to_shared(smbuf);
    const int tid = threadIdx.x;
    const int lane = tid & 31, warp = tid >> 5;
    const int warpM = warp >> 2, warpN = warp & 3;
    const int g = lane >> 2, t = lane & 3;
    const int m0 = blockIdx.y * 128;
    const int n0t = blockIdx.x * 128;

    const __half* W; __half* C; int n0;
    if (n0t < DD)            { W = g_wqh; C = qo; n0 = n0t; }
    else if (n0t < 2 * DD)   { W = g_wkh; C = ko; n0 = n0t - DD; }
    else                     { W = g_wvh; C = vo; n0 = n0t - 2 * DD; }

    float acc[4][4][4] = {};
    const int arow_f = tid >> 1;
    const int ac = (tid & 1) * 2;
    const __half* Ap = A + (size_t)(m0 + arow_f) * DD + ac * 8;
    const __half* Bp = W + (size_t)(n0 + arow_f) * DD + ac * 8;
    const uint32_t dA0 = smb + (arow_f * HSTR + ac * 4) * 4;
    const uint32_t dB0 = smb + HA_TILE * 4 + (arow_f * HSTR + ac * 4) * 4;

    const int nt = DD / 32;
    ISSUE_PROJH(0, 0);
    for (int kt = 0; kt < nt; kt++) {
        const int buf = kt & 1;
        if (kt + 1 < nt) { ISSUE_PROJH(kt + 1, buf ^ 1); cp_wait<1>(); }
        else             { cp_wait<0>(); }
        __syncthreads();
        const uint32_t* Sb = smbuf + buf * PROJH_STAGE;
        const uint32_t* Ab = Sb;
        const uint32_t* Bb = Sb + HA_TILE;
        COMPUTE_TILE_H(Ab, Bb);
        __syncthreads();
    }

    #pragma unroll
    for (int mi = 0; mi < 4; mi++) {
        int r0 = m0 + warpM * 64 + mi * 16 + g;
        #pragma unroll
        for (int ni = 0; ni < 4; ni++) {
            int c = n0 + warpN * 32 + ni * 8 + 2 * t;
            size_t i0 = (size_t)r0 * DD + c;
            size_t i1 = i0 + (size_t)8 * DD;
            *(__half2*)(C + i0) = __floats2half2_rn(acc[mi][ni][0], acc[mi][ni][1]);
            *(__half2*)(C + i1) = __floats2half2_rn(acc[mi][ni][2], acc[mi][ni][3]);
        }
    }
}

// ---------------- wo projection (fp16 mma, fp32 resid + out) -----------------
__global__ __launch_bounds__(256) void gemm_wo_h(
    const __half* __restrict__ A, const float* __restrict__ resid,
    float* __restrict__ C)
{
    extern __shared__ uint32_t smbuf[];
    const uint32_t smb = (uint32_t)__cvta_generic_to_shared(smbuf);
    const int tid = threadIdx.x;
    const int lane = tid & 31, warp = tid >> 5;
    const int warpM = warp >> 2, warpN = warp & 3;
    const int g = lane >> 2, t = lane & 3;
    const int m0 = blockIdx.y * 128, n0 = blockIdx.x * 128;

    float acc[4][4][4] = {};
    const int arow_f = tid >> 1;
    const int ac = (tid & 1) * 2;
    const __half* Ap = A + (size_t)(m0 + arow_f) * DD + ac * 8;
    const __half* Bp = g_woh + (size_t)(n0 + arow_f) * DD + ac * 8;
    const uint32_t dA0 = smb + (arow_f * HSTR + ac * 4) * 4;
    const uint32_t dB0 = smb + HA_TILE * 4 + (arow_f * HSTR + ac * 4) * 4;

    const int nt = DD / 32;
    ISSUE_PROJH(0, 0);
    for (int kt = 0; kt < nt; kt++) {
        const int buf = kt & 1;
        if (kt + 1 < nt) { ISSUE_PROJH(kt + 1, buf ^ 1); cp_wait<1>(); }
        else             { cp_wait<0>(); }
        __syncthreads();
        const uint32_t* Sb = smbuf + buf * PROJH_STAGE;
        const uint32_t* Ab = Sb;
        const uint32_t* Bb = Sb + HA_TILE;
        COMPUTE_TILE_H(Ab, Bb);
        __syncthreads();
    }

    #pragma unroll
    for (int mi = 0; mi < 4; mi++) {
        int r0 = m0 + warpM * 64 + mi * 16 + g;
        #pragma unroll
        for (int ni = 0; ni < 4; ni++) {
            int c = n0 + warpN * 32 + ni * 8 + 2 * t;
            size_t i0 = (size_t)r0 * DD + c;
            size_t i1 = i0 + (size_t)8 * DD;
            float2 r = *(const float2*)(resid + i0);
            *(float2*)(C + i0) = make_float2(acc[mi][ni][0] + r.x,
                                             acc[mi][ni][1] + r.y);
            r = *(const float2*)(resid + i1);
            *(float2*)(C + i1) = make_float2(acc[mi][ni][2] + r.x,
                                             acc[mi][ni][3] + r.y);
        }
    }
}

// ---------------- RoPE: fp16 in-place (q pre-scaled) -------------------------
__global__ void rope_h16_kernel(__half* __restrict__ qh, __half* __restrict__ kh,
                                const float* __restrict__ cosb,
                                const float* __restrict__ sinb)
{
    int idx = blockIdx.x * blockDim.x + threadIdx.x;
    int i = idx & 31;
    int th = idx >> 5;
    int t = th >> 4;
    int s = t & (SS - 1);
    float c = cosb[s * 32 + i], sn = sinb[s * 32 + i];
    size_t pi = ((size_t)th * HDD + i * 2) >> 1;
    __half2 qv = ((__half2*)qh)[pi];
    float xr = __low2float(qv), xi = __high2float(qv);
    ((__half2*)qh)[pi] = __floats2half2_rn((xr * c - xi * sn) * ATT_SCALE,
                                           (xr * sn + xi * c) * ATT_SCALE);
    __half2 kv = ((__half2*)kh)[pi];
    xr = __low2float(kv); xi = __high2float(kv);
    ((__half2*)kh)[pi] = __floats2half2_rn(xr * c - xi * sn, xr * sn + xi * c);
}

// ---------------- Flash attention (fp16 mma, fp32 softmax) -------------------
#define ASTRH 36
#define ATTH_SMEM (4 * 64 * ASTRH * 4)   // 36864 B
__global__ __launch_bounds__(128) void attn_h_kernel(
    const __half* __restrict__ Q, const __half* __restrict__ K,
    const __half* __restrict__ V, __half* __restrict__ O,
    const int* __restrict__ causal_flag)
{
    extern __shared__ uint32_t smw[];
    uint32_t* Qs = smw;
    uint32_t* Ks = Qs + 64 * ASTRH;
    uint32_t* Vt = Ks + 64 * ASTRH;   // transposed halves: [d][kpos]
    uint32_t* Ps = Vt + 64 * ASTRH;
    __half* Vth = (__half*)Vt;
    const int qt = blockIdx.x, bh = blockIdx.y;
    const int b = bh >> 4, h = bh & 15;
    const int tid = threadIdx.x;
    const int warp = tid >> 5, lane = tid & 31;
    const int g = lane >> 2, t = lane & 3;
    const int causal = *causal_flag;
    const size_t base = (size_t)b * SS * DD + (size_t)h * HDD;
    const __half* Qb = Q + base;
    const __half* Kb = K + base;
    const __half* Vb = V + base;
    const int q0 = qt * 64;

    {   // load Q tile (fp16, already scaled)
        int row = tid >> 1;
        int cw = (tid & 1) * 16;
        const uint4* src = (const uint4*)(Qb + (size_t)(q0 + row) * DD + cw * 2);
        #pragma unroll
        for (int j = 0; j < 4; j++)
            *(uint4*)&Qs[row * ASTRH + cw + j * 4] = src[j];
    }

    float m_run0 = -1e30f, m_run1 = -1e30f;
    float l_run0 = 0.f, l_run1 = 0.f;
    float Oacc[8][4] = {};
    const int mrow = warp * 16 + g;

    const int ktmax = causal ? qt : (SS / 64 - 1);
    for (int kt = 0; kt <= ktmax; kt++) {
        __syncthreads();
        {   // load K tile + transposed V tile
            int row = tid >> 1;
            int cw = (tid & 1) * 16;
            const uint4* ks = (const uint4*)(Kb + (size_t)(kt * 64 + row) * DD + cw * 2);
            #pragma unroll
            for (int j = 0; j < 4; j++)
                *(uint4*)&Ks[row * ASTRH + cw + j * 4] = ks[j];
            const __half2* vs = (const __half2*)(Vb + (size_t)(kt * 64 + row) * DD + cw * 2);
            #pragma unroll
            for (int j = 0; j < 16; j++) {
                __half2 p = vs[j];
                int c = cw * 2 + j * 2;
                Vth[(c + 0) * (ASTRH * 2) + row] = __low2half(p);
                Vth[(c + 1) * (ASTRH * 2) + row] = __high2half(p);
            }
        }
        __syncthreads();

        // S = Q @ K^T
        float sacc[8][4] = {};
        #pragma unroll
        for (int s = 0; s < 4; s++) {
            int kb = s * 8;
            uint32_t af[4];
            af[0] = Qs[mrow * ASTRH + kb + t];
            af[1] = Qs[(mrow + 8) * ASTRH + kb + t];
            af[2] = Qs[mrow * ASTRH + kb + t + 4];
            af[3] = Qs[(mrow + 8) * ASTRH + kb + t + 4];
            #pragma unroll
            for (int ni = 0; ni < 8; ni++) {
                uint32_t bf[2];
                bf[0] = Ks[(ni * 8 + g) * ASTRH + kb + t];
                bf[1] = Ks[(ni * 8 + g) * ASTRH + kb + t + 4];
                mma_f16(sacc[ni], af, bf);
            }
        }

        const int row0 = q0 + mrow, row1 = row0 + 8;
        if (causal && kt == qt) {
            #pragma unroll
            for (int ni = 0; ni < 8; ni++) {
                int c0 = kt * 64 + ni * 8 + 2 * t;
                if (c0     > row0) sacc[ni][0] = -1e30f;
                if (c0 + 1 > row0) sacc[ni][1] = -1e30f;
                if (c0     > row1) sacc[ni][2] = -1e30f;
                if (c0 + 1 > row1) sacc[ni][3] = -1e30f;
            }
        }

        float ml0 = -1e30f, ml1 = -1e30f;
        #pragma unroll
        for (int ni = 0; ni < 8; ni++) {
            ml0 = fmaxf(ml0, fmaxf(sacc[ni][0], sacc[ni][1]));
            ml1 = fmaxf(ml1, fmaxf(sacc[ni][2], sacc[ni][3]));
        }
        ml0 = fmaxf(ml0, __shfl_xor_sync(0xffffffffu, ml0, 1));
        ml0 = fmaxf(ml0, __shfl_xor_sync(0xffffffffu, ml0, 2));
        ml1 = fmaxf(ml1, __shfl_xor_sync(0xffffffffu, ml1, 1));
        ml1 = fmaxf(ml1, __shfl_xor_sync(0xffffffffu, ml1, 2));
        float mn0 = fmaxf(m_run0, ml0), mn1 = fmaxf(m_run1, ml1);
        float a0 = expf(m_run0 - mn0), a1 = expf(m_run1 - mn1);
        float ps0 = 0.f, ps1 = 0.f;
        #pragma unroll
        for (int ni = 0; ni < 8; ni++) {
            float p0 = expf(sacc[ni][0] - mn0);
            float p1 = expf(sacc[ni][1] - mn0);
            float p2 = expf(sacc[ni][2] - mn1);
            float p3 = expf(sacc[ni][3] - mn1);
            ps0 += p0 + p1; ps1 += p2 + p3;
            __half2 hp0 = __floats2half2_rn(p0, p1);
            __half2 hp1 = __floats2half2_rn(p2, p3);
            Ps[mrow * ASTRH + ni * 4 + t]       = *(uint32_t*)&hp0;
            Ps[(mrow + 8) * ASTRH + ni * 4 + t] = *(uint32_t*)&hp1;
        }
        ps0 += __shfl_xor_sync(0xffffffffu, ps0, 1);
        ps0 += __shfl_xor_sync(0xffffffffu, ps0, 2);
        ps1 += __shfl_xor_sync(0xffffffffu, ps1, 1);
        ps1 += __shfl_xor_sync(0xffffffffu, ps1, 2);
        l_run0 = l_run0 * a0 + ps0;
        l_run1 = l_run1 * a1 + ps1;
        m_run0 = mn0; m_run1 = mn1;
        #pragma unroll
        for (int ni = 0; ni < 8; ni++) {
            Oacc[ni][0] *= a0; Oacc[ni][1] *= a0;
            Oacc[ni][2] *= a1; Oacc[ni][3] *= a1;
        }
        __syncwarp();

        // O += P @ V
        #pragma unroll
        for (int s = 0; s < 4; s++) {
            int kb = s * 8;
            uint32_t af[4];
            af[0] = Ps[mrow * ASTRH + kb + t];
            af[1] = Ps[(mrow + 8) * ASTRH + kb + t];
            af[2] = Ps[mrow * ASTRH + kb + t + 4];
            af[3] = Ps[(mrow + 8) * ASTRH + kb + t + 4];
            #pragma unroll
            for (int ni = 0; ni < 8; ni++) {
                uint32_t bf[2];
                bf[0] = Vt[(ni * 8 + g) * ASTRH + kb + t];
                bf[1] = Vt[(ni * 8 + g) * ASTRH + kb + t + 4];
                mma_f16(Oacc[ni], af, bf);
            }
        }
    }

    float i0 = 1.f / l_run0, i1 = 1.f / l_run1;
    const int row0 = q0 + mrow;
    __half* dst0 = O + (size_t)(b * SS + row0) * DD + (size_t)h * HDD;
    __half* dst1 = dst0 + (size_t)8 * DD;
    #pragma unroll
    for (int ni = 0; ni < 8; ni++) {
        int d = ni * 8 + 2 * t;
        *(__half2*)(dst0 + d) = __floats2half2_rn(Oacc[ni][0] * i0, Oacc[ni][1] * i0);
        *(__half2*)(dst1 + d) = __floats2half2_rn(Oacc[ni][2] * i1, Oacc[ni][3] * i1);
    }
}

// ---------------- fused w1+w3 expert GEMM (fp16 mma) -------------------------
__global__ __launch_bounds__(256) void moe_w13_h(const __half* __restrict__ A)
{
    const int e = blockIdx.z;
    const int count = g_expcnt[e];
    const int m0 = blockIdx.y * 128;
    if (m0 >= count) return;

    extern __shared__ uint32_t smbuf[];
    __shared__ int srow[128];
    const uint32_t smb = (uint32_t)__cvta_generic_to_shared(smbuf);

    const int tid = threadIdx.x;
    if (tid < 128) {
        int r = m0 + tid;
        srow[tid] = (r < count) ? g_expslots[e * NTOK + r] : -1;
    }
    __syncthreads();

    const int lane = tid & 31, warp = tid >> 5;
    const int warpM = warp >> 2, warpN = warp & 3;
    const int g = lane >> 2, t = lane & 3;
    const int n0 = blockIdx.x * 64;
    float acc1[4][2][4] = {};
    float acc3[4][2][4] = {};

    const int arow_f = tid >> 1;
    const int ac = (tid & 1) * 2;
    const int s_a = srow[arow_f];
    const int aok = (s_a >= 0);
    const __half* aptr = A + (size_t)(aok ? (s_a >> 1) : 0) * DD + ac * 8;
    const int brow = (tid & 127) >> 1;
    const int bc = (tid & 1) * 2;
    const __half* bptr = ((tid < 128) ? g_w1h : g_w3h)
                         + (size_t)e * FF * DD + (size_t)(n0 + brow) * DD + bc * 8;
    const uint32_t bRegion = (tid < 128) ? (HA_TILE * 4) : ((HA_TILE + HB_TILE) * 4);
    const uint32_t dA0 = smb + (arow_f * HSTR + ac * 4) * 4;
    const uint32_t dB0 = smb + bRegion + (brow * HSTR + bc * 4) * 4;

#define ISSUE_W13H(tile, st) do {                                              \
    const int ko_ = (tile) * 32;                                               \
    const uint32_t o_ = (uint32_t)(st) * W13H_STAGE * 4;                       \
    cp16z(dA0 + o_,      aptr + ko_,     aok);                                 \
    cp16z(dA0 + o_ + 16, aptr + ko_ + 8, aok);                                 \
    cp16 (dB0 + o_,      bptr + ko_);                                          \
    cp16 (dB0 + o_ + 16, bptr + ko_ + 8);                                      \
    cp_commit();                                                               \
} while (0)

    const int nt = DD / 32;
    ISSUE_W13H(0, 0);
    for (int kt = 0; kt < nt; kt++) {
        const int buf = kt & 1;
        if (kt + 1 < nt) { ISSUE_W13H(kt + 1, buf ^ 1); cp_wait<1>(); }
        else             { cp_wait<0>(); }
        __syncthreads();

        const uint32_t* Sb  = smbuf + buf * W13H_STAGE;
        const uint32_t* Ab  = Sb;
        const uint32_t* B1b = Sb + HA_TILE;
        const uint32_t* B3b = Sb + HA_TILE + HB_TILE;
        #pragma unroll
        for (int s = 0; s < 2; s++) {
            int kb = s * 8;
            uint32_t bf1[2][2], bf3[2][2];
            #pragma unroll
            for (int ni = 0; ni < 2; ni++) {
                int n = warpN * 16 + ni * 8 + g;
                bf1[ni][0] = B1b[n * HSTR + kb + t];
                bf1[ni][1] = B1b[n * HSTR + kb + t + 4];
                bf3[ni][0] = B3b[n * HSTR + kb + t];
                bf3[ni][1] = B3b[n * HSTR + kb + t + 4];
            }
            #pragma unroll
            for (int mi = 0; mi < 4; mi++) {
                int m = warpM * 64 + mi * 16 + g;
                uint32_t af[4];
                af[0] = Ab[m * HSTR + kb + t];
                af[1] = Ab[(m + 8) * HSTR + kb + t];
                af[2] = Ab[m * HSTR + kb + t + 4];
                af[3] = Ab[(m + 8) * HSTR + kb + t + 4];
                #pragma unroll
                for (int ni = 0; ni < 2; ni++) {
                    mma_f16(acc1[mi][ni], af, bf1[ni]);
                    mma_f16(acc3[mi][ni], af, bf3[ni]);
                }
            }
        }
        __syncthreads();
    }

    #pragma unroll
    for (int mi = 0; mi < 4; mi++) {
        int mloc0 = warpM * 64 + mi * 16 + g;
        #pragma unroll
        for (int half = 0; half < 2; half++) {
            int mloc = mloc0 + half * 8;
            int s = srow[mloc];
            if (s < 0) continue;
            #pragma unroll
            for (int ni = 0; ni < 2; ni++) {
                int c = n0 + warpN * 16 + ni * 8 + 2 * t;
                float h1x = acc1[mi][ni][half * 2],     h1y = acc1[mi][ni][half * 2 + 1];
                float h3x = acc3[mi][ni][half * 2],     h3y = acc3[mi][ni][half * 2 + 1];
                float ox = (h1x / (1.f + expf(-h1x))) * h3x;
                float oy = (h1y / (1.f + expf(-h1y))) * h3y;
                *(__half2*)(&g_hidh[(size_t)s * FF + c]) = __floats2half2_rn(ox, oy);
            }
        }
    }
}

// ---------------- w2 expert GEMM (fp16 mma, N=128) ---------------------------
__global__ __launch_bounds__(256) void moe_w2_h()
{
    const int e = blockIdx.z;
    const int count = g_expcnt[e];
    const int m0 = blockIdx.y * 128;
    if (m0 >= count) return;

    extern __shared__ uint32_t smbuf[];
    __shared__ int srow[128];
    const uint32_t smb = (uint32_t)__cvta_generic_to_shared(smbuf);

    const int tid = threadIdx.x;
    if (tid < 128) {
        int r = m0 + tid;
        srow[tid] = (r < count) ? g_expslots[e * NTOK + r] : -1;
    }
    __syncthreads();

    const int lane = tid & 31, warp = tid >> 5;
    const int warpM = warp >> 2, warpN = warp & 3;
    const int g = lane >> 2, t = lane & 3;
    const int n0 = blockIdx.x * 128;
    float acc[4][4][4] = {};

    const int arow_f = tid >> 1;
    const int ac = (tid & 1) * 2;
    const int s_a = srow[arow_f];
    const int aok = (s_a >= 0);
    const __half* aptr = g_hidh + (size_t)(aok ? s_a : 0) * FF + ac * 8;
    const __half* bptr = g_w2h + (size_t)e * DD * FF
                         + (size_t)(n0 + arow_f) * FF + ac * 8;
    const uint32_t dA0 = smb + (arow_f * HSTR + ac * 4) * 4;
    const uint32_t dB0 = smb + HA_TILE * 4 + (arow_f * HSTR + ac * 4) * 4;

#define ISSUE_W2H(tile, st) do {                                               \
    const int ko_ = (tile) * 32;                                               \
    const uint32_t o_ = (uint32_t)(st) * PROJH_STAGE * 4;                      \
    cp16z(dA0 + o_,      aptr + ko_,     aok);                                 \
    cp16z(dA0 + o_ + 16, aptr + ko_ + 8, aok);                                 \
    cp16 (dB0 + o_,      bptr + ko_);                                          \
    cp16 (dB0 + o_ + 16, bptr + ko_ + 8);                                      \
    cp_commit();                                                               \
} while (0)

    const int nt = FF / 32;
    ISSUE_W2H(0, 0);
    for (int kt = 0; kt < nt; kt++) {
        const int buf = kt & 1;
        if (kt + 1 < nt) { ISSUE_W2H(kt + 1, buf ^ 1); cp_wait<1>(); }
        else             { cp_wait<0>(); }
        __syncthreads();

        const uint32_t* Sb = smbuf + buf * PROJH_STAGE;
        const uint32_t* Ab = Sb;
        const uint32_t* Bb = Sb + HA_TILE;
        COMPUTE_TILE_H(Ab, Bb);
        __syncthreads();
    }

    #pragma unroll
    for (int mi = 0; mi < 4; mi++) {
        int mloc0 = warpM * 64 + mi * 16 + g;
        #pragma unroll
        for (int half = 0; half < 2; half++) {
            int mloc = mloc0 + half * 8;
            int s = srow[mloc];
            if (s < 0) continue;
            #pragma unroll
            for (int ni = 0; ni < 4; ni++) {
                int c = n0 + warpN * 32 + ni * 8 + 2 * t;
                *(float2*)(&g_ypair[(size_t)s * DD + c]) =
                    make_float2(acc[mi][ni][half * 2], acc[mi][ni][half * 2 + 1]);
            }
        }
    }
}

// ---------------- router + top-2 ---------------------------------------------
__global__ void zero_counts_kernel()
{
    if (threadIdx.x < EE) g_expcnt[threadIdx.x] = 0;
}

__global__ __launch_bounds__(256) void router_kernel(
    const float* __restrict__ xn, const float* __restrict__ rw,
    const float* __restrict__ rb)
{
    int t = blockIdx.x;
    float4 xv = ((const float4*)(xn + (size_t)t * DD))[threadIdx.x];
    float lg[EE];
    #pragma unroll
    for (int e = 0; e < EE; e++) {
        float4 wv = ((const float4*)(rw + (size_t)e * DD))[threadIdx.x];
        lg[e] = xv.x * wv.x + xv.y * wv.y + xv.z * wv.z + xv.w * wv.w;
    }
    #pragma unroll
    for (int o = 16; o; o >>= 1)
        #pragma unroll
        for (int e = 0; e < EE; e++)
            lg[e] += __shfl_xor_sync(0xffffffffu, lg[e], o);
    __shared__ float sh[EE][8];
    int warp = threadIdx.x >> 5;
    if ((threadIdx.x & 31) == 0)
        #pragma unroll
        for (int e = 0; e < EE; e++) sh[e][warp] = lg[e];
    __syncthreads();
    if (threadIdx.x == 0) {
        float logits[EE];
        #pragma unroll
        for (int e = 0; e < EE; e++) {
            float s = rb[e];
            #pragma unroll
            for (int w = 0; w < 8; w++) s += sh[e][w];
            logits[e] = s;
        }
        int i0 = 0;
        #pragma unroll
        for (int e = 1; e < EE; e++) if (logits[e] > logits[i0]) i0 = e;
        int i1 = -1;
        #pragma unroll
        for (int e = 0; e < EE; e++)
            if (e != i0 && (i1 < 0 || logits[e] > logits[i1])) i1 = e;
        float ex = expf(logits[i1] - logits[i0]);
        float denom = 1.f + ex;
        float p0 = 1.f / denom, p1 = ex / denom;
        int s0 = atomicAdd(&g_expcnt[i0], 1);
        g_expslots[i0 * NTOK + s0] = 2 * t;
        g_gate[2 * t] = p0;
        int s1 = atomicAdd(&g_expcnt[i1], 1);
        g_expslots[i1 * NTOK + s1] = 2 * t + 1;
        g_gate[2 * t + 1] = p1;
    }
}

// ---------------- final combine ----------------------------------------------
__global__ __launch_bounds__(256) void combine_kernel(float* __restrict__ out)
{
    int idx = blockIdx.x * 256 + threadIdx.x;
    int t = idx >> 8;
    int col = idx & 255;
    float g0 = g_gate[2 * t], g1 = g_gate[2 * t + 1];
    float4 hv = ((const float4*)g_h)[idx];
    float4 y0 = ((const float4*)g_ypair)[(size_t)(2 * t) * 256 + col];
    float4 y1 = ((const float4*)g_ypair)[(size_t)(2 * t + 1) * 256 + col];
    float4 o;
    o.x = hv.x + g0 * y0.x + g1 * y1.x;
    o.y = hv.y + g0 * y0.y + g1 * y1.y;
    o.z = hv.z + g0 * y0.z + g1 * y1.z;
    o.w = hv.w + g0 * y0.w + g1 * y1.w;
    ((float4*)out)[idx] = o;
}

// ---------------- launch -----------------------------------------------------
extern "C" void kernel_launch(void* const* d_in, const int* in_sizes, int n_in,
                              void* d_out, int out_size)
{
    const float* q     = (const float*)d_in[0];
    const float* fcos  = (const float*)d_in[3];
    const float* fsin  = (const float*)d_in[4];
    const float* att_w = (const float*)d_in[5];
    const float* ffn_w = (const float*)d_in[6];
    const float* wq    = (const float*)d_in[7];
    const float* wk    = (const float*)d_in[8];
    const float* wv    = (const float*)d_in[9];
    const float* wo    = (const float*)d_in[10];
    const float* rw    = (const float*)d_in[11];
    const float* rb    = (const float*)d_in[12];
    const float* w1    = (const float*)d_in[13];
    const float* w2    = (const float*)d_in[14];
    const float* w3    = (const float*)d_in[15];
    const int*   causal= (const int*)d_in[16];
    float* out = (float*)d_out;

    float *p_xn, *p_h;
    __half *p_w1h, *p_w3h, *p_w2h, *p_xnh;
    __half *p_wqh, *p_wkh, *p_wvh, *p_woh;
    __half *p_qhh, *p_khh, *p_vhh, *p_atth;
    cudaGetSymbolAddress((void**)&p_xn, g_xn);
    cudaGetSymbolAddress((void**)&p_h, g_h);
    cudaGetSymbolAddress((void**)&p_w1h, g_w1h);
    cudaGetSymbolAddress((void**)&p_w3h, g_w3h);
    cudaGetSymbolAddress((void**)&p_w2h, g_w2h);
    cudaGetSymbolAddress((void**)&p_xnh, g_xnh);
    cudaGetSymbolAddress((void**)&p_wqh, g_wqh);
    cudaGetSymbolAddress((void**)&p_wkh, g_wkh);
    cudaGetSymbolAddress((void**)&p_wvh, g_wvh);
    cudaGetSymbolAddress((void**)&p_woh, g_woh);
    cudaGetSymbolAddress((void**)&p_qhh, g_qhh);
    cudaGetSymbolAddress((void**)&p_khh, g_khh);
    cudaGetSymbolAddress((void**)&p_vhh, g_vhh);
    cudaGetSymbolAddress((void**)&p_atth, g_atth);

    cudaFuncSetAttribute(attn_h_kernel,
                         cudaFuncAttributeMaxDynamicSharedMemorySize, ATTH_SMEM);
    cudaFuncSetAttribute(gemm_qkv_h,
                         cudaFuncAttributeMaxDynamicSharedMemorySize, PROJH_SMEM);
    cudaFuncSetAttribute(gemm_wo_h,
                         cudaFuncAttributeMaxDynamicSharedMemorySize, PROJH_SMEM);
    cudaFuncSetAttribute(moe_w13_h,
                         cudaFuncAttributeMaxDynamicSharedMemorySize, W13H_SMEM);
    cudaFuncSetAttribute(moe_w2_h,
                         cudaFuncAttributeMaxDynamicSharedMemorySize, PROJH_SMEM);

    // 0. weight conversions to fp16 (coalesced, MLP=4: block = 1024 float4)
    const int nWB = (EE * FF * DD / 4) / 1024;   // 8192 blocks
    cvt_h4c_kernel<<<nWB, 256>>>((const float4*)w1, (__half2*)p_w1h);
    cvt_h4c_kernel<<<nWB, 256>>>((const float4*)w3, (__half2*)p_w3h);
    cvt_h4c_kernel<<<nWB, 256>>>((const float4*)w2, (__half2*)p_w2h);
    const int nDB = (DD * DD / 4) / 1024;        // 256 blocks
    cvt_h4c_kernel<<<nDB, 256>>>((const float4*)wq, (__half2*)p_wqh);
    cvt_h4c_kernel<<<nDB, 256>>>((const float4*)wk, (__half2*)p_wkh);
    cvt_h4c_kernel<<<nDB, 256>>>((const float4*)wv, (__half2*)p_wvh);
    cvt_h4c_kernel<<<nDB, 256>>>((const float4*)wo, (__half2*)p_woh);

    // 1. qn = rmsnorm(q) -> fp16
    rmsnorm_kernel<<<NTOK, 256>>>(q, att_w, (float*)nullptr, p_xnh);

    // 2. fused QKV projection (fp16 mma, fp16 out)
    gemm_qkv_h<<<dim3(3 * DD / 128, NTOK / 128), 256, PROJH_SMEM>>>(
        p_xnh, p_qhh, p_khh, p_vhh);

    // 3. RoPE in place on fp16 q/k (q pre-scaled)
    rope_h16_kernel<<<(NTOK * HH * (HDD / 2)) / 256, 256>>>(
        p_qhh, p_khh, fcos, fsin);

    // 4. flash attention (fp16 mma) -> fp16 out
    attn_h_kernel<<<dim3(SS / 64, BB * HH), 128, ATTH_SMEM>>>(
        p_qhh, p_khh, p_vhh, p_atth, causal);

    // 5. h = q + att @ wo^T
    gemm_wo_h<<<dim3(DD / 128, NTOK / 128), 256, PROJH_SMEM>>>(
        p_atth, q, p_h);

    // 6. hn = rmsnorm(h)
    rmsnorm_kernel<<<NTOK, 256>>>(p_h, ffn_w, p_xn, p_xnh);

    // 7. routing
    zero_counts_kernel<<<1, 32>>>();
    router_kernel<<<NTOK, 256>>>(p_xn, rw, rb);

    // 8. MoE (fp16 mma)
    moe_w13_h<<<dim3(FF / 64, NTOK / 128, EE), 256, W13H_SMEM>>>(p_xnh);
    moe_w2_h<<<dim3(DD / 128, NTOK / 128, EE), 256, PROJH_SMEM>>>();

    // 9. combine
    combine_kernel<<<NTOK, 256>>>(out);
}

// round 16
// speedup vs baseline: 1.0847x; 1.0065x over previous
#include <cuda_runtime.h>
#include <cuda_fp16.h>
#include <math.h>
#include <stdint.h>

// Problem constants
#define BB 4
#define SS 1024
#define DD 1024
#define HH 16
#define HDD 64
#define EE 8
#define FF 4096
#define NTOK 4096      // B*S
#define NSLOT 8192     // NTOK * K(=2)
#define RMS_EPS 1e-6f
#define ATT_SCALE 0.125f   // 1/sqrt(64)

// ---------------- scratch (static device globals) ---------------------------
__device__ float g_xn[NTOK * DD];
__device__ float g_h[NTOK * DD];
__device__ float g_ypair[(size_t)NSLOT * DD];
__device__ float g_gate[NSLOT];
__device__ int   g_expcnt[EE];
__device__ int   g_expslots[EE * NTOK];
// fp16 operands
__device__ __half g_w1h[(size_t)EE * FF * DD];
__device__ __half g_w3h[(size_t)EE * FF * DD];
__device__ __half g_w2h[(size_t)EE * DD * FF];
__device__ __half g_wqh[DD * DD];
__device__ __half g_wkh[DD * DD];
__device__ __half g_wvh[DD * DD];
__device__ __half g_woh[DD * DD];
__device__ __half g_xnh[NTOK * DD];
__device__ __half g_qhh[NTOK * DD];   // q (fp16; rotated+scaled in place by rope)
__device__ __half g_khh[NTOK * DD];   // k (fp16; rotated in place by rope)
__device__ __half g_vhh[NTOK * DD];
__device__ __half g_atth[NTOK * DD];  // attention output (fp16)
__device__ __half g_hidh[(size_t)NSLOT * FF];

// ---------------- helpers ---------------------------------------------------
__device__ __forceinline__ void mma_f16(float* c, const uint32_t* a, const uint32_t* b) {
    asm volatile(
        "mma.sync.aligned.m16n8k16.row.col.f32.f16.f16.f32 "
        "{%0,%1,%2,%3}, {%4,%5,%6,%7}, {%8,%9}, {%0,%1,%2,%3};\n"
        : "+f"(c[0]), "+f"(c[1]), "+f"(c[2]), "+f"(c[3])
        : "r"(a[0]), "r"(a[1]), "r"(a[2]), "r"(a[3]), "r"(b[0]), "r"(b[1]));
}

__device__ __forceinline__ void cp16(uint32_t dst, const void* src) {
    asm volatile("cp.async.cg.shared.global [%0], [%1], 16;\n"
                 :: "r"(dst), "l"(src));
}
__device__ __forceinline__ void cp16z(uint32_t dst, const void* src, int ok) {
    asm volatile("cp.async.cg.shared.global [%0], [%1], 16, %2;\n"
                 :: "r"(dst), "l"(src), "r"(ok ? 16 : 0));
}
__device__ __forceinline__ void cp_commit() {
    asm volatile("cp.async.commit_group;\n" ::: "memory");
}
template <int N>
__device__ __forceinline__ void cp_wait() {
    asm volatile("cp.async.wait_group %0;\n" :: "n"(N) : "memory");
}

// ---- fp16 smem tiles: 32-k row = 16 words, stride 20 words ------------------
#define HSTR 20
#define HA_TILE (128 * HSTR)                  // 2560 words
#define HB_TILE (64 * HSTR)                   // 1280 words
#define W13H_STAGE (HA_TILE + 2 * HB_TILE)
#define W13H_SMEM  (2 * W13H_STAGE * 4)       // 40960 B
#define PROJH_STAGE (2 * HA_TILE)             // A(128) + B(128)
#define PROJH_SMEM  (2 * PROJH_STAGE * 4)     // 40960 B

// ---------------- fp32 -> fp16 conversion (coalesced, MLP=4) -----------------
__global__ __launch_bounds__(256) void cvt_h4c_kernel(
    const float4* __restrict__ src, __half2* __restrict__ dst)
{
    int base = blockIdx.x * 1024 + threadIdx.x;
    #pragma unroll
    for (int k = 0; k < 4; k++) {
        int i = base + k * 256;
        float4 v = src[i];
        dst[2 * i]     = __floats2half2_rn(v.x, v.y);
        dst[2 * i + 1] = __floats2half2_rn(v.z, v.w);
    }
}

// ---------------- RMSNorm (fp32 optional + fp16 out) -------------------------
__global__ __launch_bounds__(256) void rmsnorm_kernel(
    const float* __restrict__ x, const float* __restrict__ w,
    float* __restrict__ out, __half* __restrict__ outh)
{
    int t = blockIdx.x;
    const float4* xr = (const float4*)(x + (size_t)t * DD);
    float4 v = xr[threadIdx.x];
    float ss = v.x * v.x + v.y * v.y + v.z * v.z + v.w * v.w;
    #pragma unroll
    for (int o = 16; o; o >>= 1) ss += __shfl_xor_sync(0xffffffffu, ss, o);
    __shared__ float sh[8];
    __shared__ float stot;
    int warp = threadIdx.x >> 5;
    if ((threadIdx.x & 31) == 0) sh[warp] = ss;
    __syncthreads();
    if (threadIdx.x == 0) {
        float s = 0.f;
        #pragma unroll
        for (int i = 0; i < 8; i++) s += sh[i];
        stot = rsqrtf(s / (float)DD + RMS_EPS);
    }
    __syncthreads();
    float sc = stot;
    float4 wv = ((const float4*)w)[threadIdx.x];
    float4 o;
    o.x = v.x * sc * wv.x; o.y = v.y * sc * wv.y;
    o.z = v.z * sc * wv.z; o.w = v.w * sc * wv.w;
    if (out) ((float4*)(out + (size_t)t * DD))[threadIdx.x] = o;
    __half2* dh = (__half2*)(outh + (size_t)t * DD);
    dh[threadIdx.x * 2]     = __floats2half2_rn(o.x, o.y);
    dh[threadIdx.x * 2 + 1] = __floats2half2_rn(o.z, o.w);
}

// ---------------- dense fp16 GEMM core macros --------------------------------
#define ISSUE_PROJH(tile, st) do {                                             \
    const int ko_ = (tile) * 32;                                               \
    const uint32_t o_ = (uint32_t)(st) * PROJH_STAGE * 4;                      \
    cp16(dA0 + o_,      Ap + ko_);                                             \
    cp16(dA0 + o_ + 16, Ap + ko_ + 8);                                         \
    cp16(dB0 + o_,      Bp + ko_);                                             \
    cp16(dB0 + o_ + 16, Bp + ko_ + 8);                                         \
    cp_commit();                                                               \
} while (0)

#define COMPUTE_TILE_H(Ab, Bb)                                                 \
    _Pragma("unroll")                                                          \
    for (int s = 0; s < 2; s++) {                                              \
        int kb = s * 8;                                                        \
        uint32_t bf[4][2];                                                     \
        _Pragma("unroll")                                                      \
        for (int ni = 0; ni < 4; ni++) {                                       \
            int n = warpN * 32 + ni * 8 + g;                                   \
            bf[ni][0] = (Bb)[n * HSTR + kb + t];                               \
            bf[ni][1] = (Bb)[n * HSTR + kb + t + 4];                           \
        }                                                                      \
        _Pragma("unroll")                                                      \
        for (int mi = 0; mi < 4; mi++) {                                       \
            int m = warpM * 64 + mi * 16 + g;                                  \
            uint32_t af[4];                                                    \
            af[0] = (Ab)[m * HSTR + kb + t];                                   \
            af[1] = (Ab)[(m + 8) * HSTR + kb + t];                             \
            af[2] = (Ab)[m * HSTR + kb + t + 4];                               \
            af[3] = (Ab)[(m + 8) * HSTR + kb + t + 4];                         \
            _Pragma("unroll")                                                  \
            for (int ni = 0; ni < 4; ni++)                                     \
                mma_f16(acc[mi][ni], af, bf[ni]);                              \
        }                                                                      \
    }

// ---------------- fused QKV projection (fp16 mma, fp16 out) ------------------
__global__ __launch_bounds__(256) void gemm_qkv_h(
    const __half* __restrict__ A,
    __half* __restrict__ qo, __half* __restrict__ ko, __half* __restrict__ vo)
{
    extern __shared__ uint32_t smbuf[];
    const uint32_t smb = (uint32_t)__cvta_generic_to_shared(smbuf);
    const int tid = threadIdx.x;
    const int lane = tid & 31, warp = tid >> 5;
    const int warpM = warp >> 2, warpN = warp & 3;
    const int g = lane >> 2, t = lane & 3;
    const int m0 = blockIdx.y * 128;
    const int n0t = blockIdx.x * 128;

    const __half* W; __half* C; int n0;
    if (n0t < DD)            { W = g_wqh; C = qo; n0 = n0t; }
    else if (n0t < 2 * DD)   { W = g_wkh; C = ko; n0 = n0t - DD; }
    else                     { W = g_wvh; C = vo; n0 = n0t - 2 * DD; }

    float acc[4][4][4] = {};
    const int arow_f = tid >> 1;
    const int ac = (tid & 1) * 2;
    const __half* Ap = A + (size_t)(m0 + arow_f) * DD + ac * 8;
    const __half* Bp = W + (size_t)(n0 + arow_f) * DD + ac * 8;
    const uint32_t dA0 = smb + (arow_f * HSTR + ac * 4) * 4;
    const uint32_t dB0 = smb + HA_TILE * 4 + (arow_f * HSTR + ac * 4) * 4;

    const int nt = DD / 32;
    ISSUE_PROJH(0, 0);
    for (int kt = 0; kt < nt; kt++) {
        const int buf = kt & 1;
        if (kt + 1 < nt) { ISSUE_PROJH(kt + 1, buf ^ 1); cp_wait<1>(); }
        else             { cp_wait<0>(); }
        __syncthreads();
        const uint32_t* Sb = smbuf + buf * PROJH_STAGE;
        const uint32_t* Ab = Sb;
        const uint32_t* Bb = Sb + HA_TILE;
        COMPUTE_TILE_H(Ab, Bb);
        __syncthreads();
    }

    #pragma unroll
    for (int mi = 0; mi < 4; mi++) {
        int r0 = m0 + warpM * 64 + mi * 16 + g;
        #pragma unroll
        for (int ni = 0; ni < 4; ni++) {
            int c = n0 + warpN * 32 + ni * 8 + 2 * t;
            size_t i0 = (size_t)r0 * DD + c;
            size_t i1 = i0 + (size_t)8 * DD;
            *(__half2*)(C + i0) = __floats2half2_rn(acc[mi][ni][0], acc[mi][ni][1]);
            *(__half2*)(C + i1) = __floats2half2_rn(acc[mi][ni][2], acc[mi][ni][3]);
        }
    }
}

// ---------------- wo projection (fp16 mma, fp32 resid + out) -----------------
__global__ __launch_bounds__(256) void gemm_wo_h(
    const __half* __restrict__ A, const float* __restrict__ resid,
    float* __restrict__ C)
{
    extern __shared__ uint32_t smbuf[];
    const uint32_t smb = (uint32_t)__cvta_generic_to_shared(smbuf);
    const int tid = threadIdx.x;
    const int lane = tid & 31, warp = tid >> 5;
    const int warpM = warp >> 2, warpN = warp & 3;
    const int g = lane >> 2, t = lane & 3;
    const int m0 = blockIdx.y * 128, n0 = blockIdx.x * 128;

    float acc[4][4][4] = {};
    const int arow_f = tid >> 1;
    const int ac = (tid & 1) * 2;
    const __half* Ap = A + (size_t)(m0 + arow_f) * DD + ac * 8;
    const __half* Bp = g_woh + (size_t)(n0 + arow_f) * DD + ac * 8;
    const uint32_t dA0 = smb + (arow_f * HSTR + ac * 4) * 4;
    const uint32_t dB0 = smb + HA_TILE * 4 + (arow_f * HSTR + ac * 4) * 4;

    const int nt = DD / 32;
    ISSUE_PROJH(0, 0);
    for (int kt = 0; kt < nt; kt++) {
        const int buf = kt & 1;
        if (kt + 1 < nt) { ISSUE_PROJH(kt + 1, buf ^ 1); cp_wait<1>(); }
        else             { cp_wait<0>(); }
        __syncthreads();
        const uint32_t* Sb = smbuf + buf * PROJH_STAGE;
        const uint32_t* Ab = Sb;
        const uint32_t* Bb = Sb + HA_TILE;
        COMPUTE_TILE_H(Ab, Bb);
        __syncthreads();
    }

    #pragma unroll
    for (int mi = 0; mi < 4; mi++) {
        int r0 = m0 + warpM * 64 + mi * 16 + g;
        #pragma unroll
        for (int ni = 0; ni < 4; ni++) {
            int c = n0 + warpN * 32 + ni * 8 + 2 * t;
            size_t i0 = (size_t)r0 * DD + c;
            size_t i1 = i0 + (size_t)8 * DD;
            float2 r = *(const float2*)(resid + i0);
            *(float2*)(C + i0) = make_float2(acc[mi][ni][0] + r.x,
                                             acc[mi][ni][1] + r.y);
            r = *(const float2*)(resid + i1);
            *(float2*)(C + i1) = make_float2(acc[mi][ni][2] + r.x,
                                             acc[mi][ni][3] + r.y);
        }
    }
}

// ---------------- RoPE: fp16 in-place (q pre-scaled) -------------------------
__global__ void rope_h16_kernel(__half* __restrict__ qh, __half* __restrict__ kh,
                                const float* __restrict__ cosb,
                                const float* __restrict__ sinb)
{
    int idx = blockIdx.x * blockDim.x + threadIdx.x;
    int i = idx & 31;
    int th = idx >> 5;
    int t = th >> 4;
    int s = t & (SS - 1);
    float c = cosb[s * 32 + i], sn = sinb[s * 32 + i];
    size_t pi = ((size_t)th * HDD + i * 2) >> 1;
    __half2 qv = ((__half2*)qh)[pi];
    float xr = __low2float(qv), xi = __high2float(qv);
    ((__half2*)qh)[pi] = __floats2half2_rn((xr * c - xi * sn) * ATT_SCALE,
                                           (xr * sn + xi * c) * ATT_SCALE);
    __half2 kv = ((__half2*)kh)[pi];
    xr = __low2float(kv); xi = __high2float(kv);
    ((__half2*)kh)[pi] = __floats2half2_rn(xr * c - xi * sn, xr * sn + xi * c);
}

// ---------------- Flash attention (fp16 mma, fp32 softmax) -------------------
#define ASTRH 36
#define ATTH_SMEM (4 * 64 * ASTRH * 4)   // 36864 B
__global__ __launch_bounds__(128) void attn_h_kernel(
    const __half* __restrict__ Q, const __half* __restrict__ K,
    const __half* __restrict__ V, __half* __restrict__ O,
    const int* __restrict__ causal_flag)
{
    extern __shared__ uint32_t smw[];
    uint32_t* Qs = smw;
    uint32_t* Ks = Qs + 64 * ASTRH;
    uint32_t* Vt = Ks + 64 * ASTRH;   // transposed halves: [d][kpos]
    uint32_t* Ps = Vt + 64 * ASTRH;
    __half* Vth = (__half*)Vt;
    const int qt = blockIdx.x, bh = blockIdx.y;
    const int b = bh >> 4, h = bh & 15;
    const int tid = threadIdx.x;
    const int warp = tid >> 5, lane = tid & 31;
    const int g = lane >> 2, t = lane & 3;
    const int causal = *causal_flag;
    const size_t base = (size_t)b * SS * DD + (size_t)h * HDD;
    const __half* Qb = Q + base;
    const __half* Kb = K + base;
    const __half* Vb = V + base;
    const int q0 = qt * 64;

    {
        int row = tid >> 1;
        int cw = (tid & 1) * 16;
        const uint4* src = (const uint4*)(Qb + (size_t)(q0 + row) * DD + cw * 2);
        #pragma unroll
        for (int j = 0; j < 4; j++)
            *(uint4*)&Qs[row * ASTRH + cw + j * 4] = src[j];
    }

    float m_run0 = -1e30f, m_run1 = -1e30f;
    float l_run0 = 0.f, l_run1 = 0.f;
    float Oacc[8][4] = {};
    const int mrow = warp * 16 + g;

    const int ktmax = causal ? qt : (SS / 64 - 1);
    for (int kt = 0; kt <= ktmax; kt++) {
        __syncthreads();
        {
            int row = tid >> 1;
            int cw = (tid & 1) * 16;
            const uint4* ks = (const uint4*)(Kb + (size_t)(kt * 64 + row) * DD + cw * 2);
            #pragma unroll
            for (int j = 0; j < 4; j++)
                *(uint4*)&Ks[row * ASTRH + cw + j * 4] = ks[j];
            const __half2* vs = (const __half2*)(Vb + (size_t)(kt * 64 + row) * DD + cw * 2);
            #pragma unroll
            for (int j = 0; j < 16; j++) {
                __half2 p = vs[j];
                int c = cw * 2 + j * 2;
                Vth[(c + 0) * (ASTRH * 2) + row] = __low2half(p);
                Vth[(c + 1) * (ASTRH * 2) + row] = __high2half(p);
            }
        }
        __syncthreads();

        float sacc[8][4] = {};
        #pragma unroll
        for (int s = 0; s < 4; s++) {
            int kb = s * 8;
            uint32_t af[4];
            af[0] = Qs[mrow * ASTRH + kb + t];
            af[1] = Qs[(mrow + 8) * ASTRH + kb + t];
            af[2] = Qs[mrow * ASTRH + kb + t + 4];
            af[3] = Qs[(mrow + 8) * ASTRH + kb + t + 4];
            #pragma unroll
            for (int ni = 0; ni < 8; ni++) {
                uint32_t bf[2];
                bf[0] = Ks[(ni * 8 + g) * ASTRH + kb + t];
                bf[1] = Ks[(ni * 8 + g) * ASTRH + kb + t + 4];
                mma_f16(sacc[ni], af, bf);
            }
        }

        const int row0 = q0 + mrow, row1 = row0 + 8;
        if (causal && kt == qt) {
            #pragma unroll
            for (int ni = 0; ni < 8; ni++) {
                int c0 = kt * 64 + ni * 8 + 2 * t;
                if (c0     > row0) sacc[ni][0] = -1e30f;
                if (c0 + 1 > row0) sacc[ni][1] = -1e30f;
                if (c0     > row1) sacc[ni][2] = -1e30f;
                if (c0 + 1 > row1) sacc[ni][3] = -1e30f;
            }
        }

        float ml0 = -1e30f, ml1 = -1e30f;
        #pragma unroll
        for (int ni = 0; ni < 8; ni++) {
            ml0 = fmaxf(ml0, fmaxf(sacc[ni][0], sacc[ni][1]));
            ml1 = fmaxf(ml1, fmaxf(sacc[ni][2], sacc[ni][3]));
        }
        ml0 = fmaxf(ml0, __shfl_xor_sync(0xffffffffu, ml0, 1));
        ml0 = fmaxf(ml0, __shfl_xor_sync(0xffffffffu, ml0, 2));
        ml1 = fmaxf(ml1, __shfl_xor_sync(0xffffffffu, ml1, 1));
        ml1 = fmaxf(ml1, __shfl_xor_sync(0xffffffffu, ml1, 2));
        float mn0 = fmaxf(m_run0, ml0), mn1 = fmaxf(m_run1, ml1);
        float a0 = expf(m_run0 - mn0), a1 = expf(m_run1 - mn1);
        float ps0 = 0.f, ps1 = 0.f;
        #pragma unroll
        for (int ni = 0; ni < 8; ni++) {
            float p0 = expf(sacc[ni][0] - mn0);
            float p1 = expf(sacc[ni][1] - mn0);
            float p2 = expf(sacc[ni][2] - mn1);
            float p3 = expf(sacc[ni][3] - mn1);
            ps0 += p0 + p1; ps1 += p2 + p3;
            __half2 hp0 = __floats2half2_rn(p0, p1);
            __half2 hp1 = __floats2half2_rn(p2, p3);
            Ps[mrow * ASTRH + ni * 4 + t]       = *(uint32_t*)&hp0;
            Ps[(mrow + 8) * ASTRH + ni * 4 + t] = *(uint32_t*)&hp1;
        }
        ps0 += __shfl_xor_sync(0xffffffffu, ps0, 1);
        ps0 += __shfl_xor_sync(0xffffffffu, ps0, 2);
        ps1 += __shfl_xor_sync(0xffffffffu, ps1, 1);
        ps1 += __shfl_xor_sync(0xffffffffu, ps1, 2);
        l_run0 = l_run0 * a0 + ps0;
        l_run1 = l_run1 * a1 + ps1;
        m_run0 = mn0; m_run1 = mn1;
        #pragma unroll
        for (int ni = 0; ni < 8; ni++) {
            Oacc[ni][0] *= a0; Oacc[ni][1] *= a0;
            Oacc[ni][2] *= a1; Oacc[ni][3] *= a1;
        }
        __syncwarp();

        #pragma unroll
        for (int s = 0; s < 4; s++) {
            int kb = s * 8;
            uint32_t af[4];
            af[0] = Ps[mrow * ASTRH + kb + t];
            af[1] = Ps[(mrow + 8) * ASTRH + kb + t];
            af[2] = Ps[mrow * ASTRH + kb + t + 4];
            af[3] = Ps[(mrow + 8) * ASTRH + kb + t + 4];
            #pragma unroll
            for (int ni = 0; ni < 8; ni++) {
                uint32_t bf[2];
                bf[0] = Vt[(ni * 8 + g) * ASTRH + kb + t];
                bf[1] = Vt[(ni * 8 + g) * ASTRH + kb + t + 4];
                mma_f16(Oacc[ni], af, bf);
            }
        }
    }

    float i0 = 1.f / l_run0, i1 = 1.f / l_run1;
    const int row0 = q0 + mrow;
    __half* dst0 = O + (size_t)(b * SS + row0) * DD + (size_t)h * HDD;
    __half* dst1 = dst0 + (size_t)8 * DD;
    #pragma unroll
    for (int ni = 0; ni < 8; ni++) {
        int d = ni * 8 + 2 * t;
        *(__half2*)(dst0 + d) = __floats2half2_rn(Oacc[ni][0] * i0, Oacc[ni][1] * i0);
        *(__half2*)(dst1 + d) = __floats2half2_rn(Oacc[ni][2] * i1, Oacc[ni][3] * i1);
    }
}

// ---------------- fused w1+w3 expert GEMM (fp16 mma) -------------------------
__global__ __launch_bounds__(256) void moe_w13_h(const __half* __restrict__ A)
{
    const int e = blockIdx.z;
    const int count = g_expcnt[e];
    const int m0 = blockIdx.y * 128;
    if (m0 >= count) return;

    extern __shared__ uint32_t smbuf[];
    __shared__ int srow[128];
    const uint32_t smb = (uint32_t)__cvta_generic_to_shared(smbuf);

    const int tid = threadIdx.x;
    if (tid < 128) {
        int r = m0 + tid;
        srow[tid] = (r < count) ? g_expslots[e * NTOK + r] : -1;
    }
    __syncthreads();

    const int lane = tid & 31, warp = tid >> 5;
    const int warpM = warp >> 2, warpN = warp & 3;
    const int g = lane >> 2, t = lane & 3;
    const int n0 = blockIdx.x * 64;
    float acc1[4][2][4] = {};
    float acc3[4][2][4] = {};

    const int arow_f = tid >> 1;
    const int ac = (tid & 1) * 2;
    const int s_a = srow[arow_f];
    const int aok = (s_a >= 0);
    const __half* aptr = A + (size_t)(aok ? (s_a >> 1) : 0) * DD + ac * 8;
    const int brow = (tid & 127) >> 1;
    const int bc = (tid & 1) * 2;
    const __half* bptr = ((tid < 128) ? g_w1h : g_w3h)
                         + (size_t)e * FF * DD + (size_t)(n0 + brow) * DD + bc * 8;
    const uint32_t bRegion = (tid < 128) ? (HA_TILE * 4) : ((HA_TILE + HB_TILE) * 4);
    const uint32_t dA0 = smb + (arow_f * HSTR + ac * 4) * 4;
    const uint32_t dB0 = smb + bRegion + (brow * HSTR + bc * 4) * 4;

#define ISSUE_W13H(tile, st) do {                                              \
    const int ko_ = (tile) * 32;                                               \
    const uint32_t o_ = (uint32_t)(st) * W13H_STAGE * 4;                       \
    cp16z(dA0 + o_,      aptr + ko_,     aok);                                 \
    cp16z(dA0 + o_ + 16, aptr + ko_ + 8, aok);                                 \
    cp16 (dB0 + o_,      bptr + ko_);                                          \
    cp16 (dB0 + o_ + 16, bptr + ko_ + 8);                                      \
    cp_commit();                                                               \
} while (0)

    const int nt = DD / 32;
    ISSUE_W13H(0, 0);
    for (int kt = 0; kt < nt; kt++) {
        const int buf = kt & 1;
        if (kt + 1 < nt) { ISSUE_W13H(kt + 1, buf ^ 1); cp_wait<1>(); }
        else             { cp_wait<0>(); }
        __syncthreads();

        const uint32_t* Sb  = smbuf + buf * W13H_STAGE;
        const uint32_t* Ab  = Sb;
        const uint32_t* B1b = Sb + HA_TILE;
        const uint32_t* B3b = Sb + HA_TILE + HB_TILE;
        #pragma unroll
        for (int s = 0; s < 2; s++) {
            int kb = s * 8;
            uint32_t bf1[2][2], bf3[2][2];
            #pragma unroll
            for (int ni = 0; ni < 2; ni++) {
                int n = warpN * 16 + ni * 8 + g;
                bf1[ni][0] = B1b[n * HSTR + kb + t];
                bf1[ni][1] = B1b[n * HSTR + kb + t + 4];
                bf3[ni][0] = B3b[n * HSTR + kb + t];
                bf3[ni][1] = B3b[n * HSTR + kb + t + 4];
            }
            #pragma unroll
            for (int mi = 0; mi < 4; mi++) {
                int m = warpM * 64 + mi * 16 + g;
                uint32_t af[4];
                af[0] = Ab[m * HSTR + kb + t];
                af[1] = Ab[(m + 8) * HSTR + kb + t];
                af[2] = Ab[m * HSTR + kb + t + 4];
                af[3] = Ab[(m + 8) * HSTR + kb + t + 4];
                #pragma unroll
                for (int ni = 0; ni < 2; ni++) {
                    mma_f16(acc1[mi][ni], af, bf1[ni]);
                    mma_f16(acc3[mi][ni], af, bf3[ni]);
                }
            }
        }
        __syncthreads();
    }

    #pragma unroll
    for (int mi = 0; mi < 4; mi++) {
        int mloc0 = warpM * 64 + mi * 16 + g;
        #pragma unroll
        for (int half = 0; half < 2; half++) {
            int mloc = mloc0 + half * 8;
            int s = srow[mloc];
            if (s < 0) continue;
            #pragma unroll
            for (int ni = 0; ni < 2; ni++) {
                int c = n0 + warpN * 16 + ni * 8 + 2 * t;
                float h1x = acc1[mi][ni][half * 2],     h1y = acc1[mi][ni][half * 2 + 1];
                float h3x = acc3[mi][ni][half * 2],     h3y = acc3[mi][ni][half * 2 + 1];
                float ox = (h1x / (1.f + expf(-h1x))) * h3x;
                float oy = (h1y / (1.f + expf(-h1y))) * h3y;
                *(__half2*)(&g_hidh[(size_t)s * FF + c]) = __floats2half2_rn(ox, oy);
            }
        }
    }
}

// ---------------- w2 expert GEMM (fp16 mma, N=128) ---------------------------
__global__ __launch_bounds__(256) void moe_w2_h()
{
    const int e = blockIdx.z;
    const int count = g_expcnt[e];
    const int m0 = blockIdx.y * 128;
    if (m0 >= count) return;

    extern __shared__ uint32_t smbuf[];
    __shared__ int srow[128];
    const uint32_t smb = (uint32_t)__cvta_generic_to_shared(smbuf);

    const int tid = threadIdx.x;
    if (tid < 128) {
        int r = m0 + tid;
        srow[tid] = (r < count) ? g_expslots[e * NTOK + r] : -1;
    }
    __syncthreads();

    const int lane = tid & 31, warp = tid >> 5;
    const int warpM = warp >> 2, warpN = warp & 3;
    const int g = lane >> 2, t = lane & 3;
    const int n0 = blockIdx.x * 128;
    float acc[4][4][4] = {};

    const int arow_f = tid >> 1;
    const int ac = (tid & 1) * 2;
    const int s_a = srow[arow_f];
    const int aok = (s_a >= 0);
    const __half* aptr = g_hidh + (size_t)(aok ? s_a : 0) * FF + ac * 8;
    const __half* bptr = g_w2h + (size_t)e * DD * FF
                         + (size_t)(n0 + arow_f) * FF + ac * 8;
    const uint32_t dA0 = smb + (arow_f * HSTR + ac * 4) * 4;
    const uint32_t dB0 = smb + HA_TILE * 4 + (arow_f * HSTR + ac * 4) * 4;

#define ISSUE_W2H(tile, st) do {                                               \
    const int ko_ = (tile) * 32;                                               \
    const uint32_t o_ = (uint32_t)(st) * PROJH_STAGE * 4;                      \
    cp16z(dA0 + o_,      aptr + ko_,     aok);                                 \
    cp16z(dA0 + o_ + 16, aptr + ko_ + 8, aok);                                 \
    cp16 (dB0 + o_,      bptr + ko_);                                          \
    cp16 (dB0 + o_ + 16, bptr + ko_ + 8);                                      \
    cp_commit();                                                               \
} while (0)

    const int nt = FF / 32;
    ISSUE_W2H(0, 0);
    for (int kt = 0; kt < nt; kt++) {
        const int buf = kt & 1;
        if (kt + 1 < nt) { ISSUE_W2H(kt + 1, buf ^ 1); cp_wait<1>(); }
        else             { cp_wait<0>(); }
        __syncthreads();

        const uint32_t* Sb = smbuf + buf * PROJH_STAGE;
        const uint32_t* Ab = Sb;
        const uint32_t* Bb = Sb + HA_TILE;
        COMPUTE_TILE_H(Ab, Bb);
        __syncthreads();
    }

    #pragma unroll
    for (int mi = 0; mi < 4; mi++) {
        int mloc0 = warpM * 64 + mi * 16 + g;
        #pragma unroll
        for (int half = 0; half < 2; half++) {
            int mloc = mloc0 + half * 8;
            int s = srow[mloc];
            if (s < 0) continue;
            #pragma unroll
            for (int ni = 0; ni < 4; ni++) {
                int c = n0 + warpN * 32 + ni * 8 + 2 * t;
                *(float2*)(&g_ypair[(size_t)s * DD + c]) =
                    make_float2(acc[mi][ni][half * 2], acc[mi][ni][half * 2 + 1]);
            }
        }
    }
}

// ---------------- router + top-2 ---------------------------------------------
__global__ void zero_counts_kernel()
{
    if (threadIdx.x < EE) g_expcnt[threadIdx.x] = 0;
}

__global__ __launch_bounds__(256) void router_kernel(
    const float* __restrict__ xn, const float* __restrict__ rw,
    const float* __restrict__ rb)
{
    int t = blockIdx.x;
    float4 xv = ((const float4*)(xn + (size_t)t * DD))[threadIdx.x];
    float lg[EE];
    #pragma unroll
    for (int e = 0; e < EE; e++) {
        float4 wv = ((const float4*)(rw + (size_t)e * DD))[threadIdx.x];
        lg[e] = xv.x * wv.x + xv.y * wv.y + xv.z * wv.z + xv.w * wv.w;
    }
    #pragma unroll
    for (int o = 16; o; o >>= 1)
        #pragma unroll
        for (int e = 0; e < EE; e++)
            lg[e] += __shfl_xor_sync(0xffffffffu, lg[e], o);
    __shared__ float sh[EE][8];
    int warp = threadIdx.x >> 5;
    if ((threadIdx.x & 31) == 0)
        #pragma unroll
        for (int e = 0; e < EE; e++) sh[e][warp] = lg[e];
    __syncthreads();
    if (threadIdx.x == 0) {
        float logits[EE];
        #pragma unroll
        for (int e = 0; e < EE; e++) {
            float s = rb[e];
            #pragma unroll
            for (int w = 0; w < 8; w++) s += sh[e][w];
            logits[e] = s;
        }
        int i0 = 0;
        #pragma unroll
        for (int e = 1; e < EE; e++) if (logits[e] > logits[i0]) i0 = e;
        int i1 = -1;
        #pragma unroll
        for (int e = 0; e < EE; e++)
            if (e != i0 && (i1 < 0 || logits[e] > logits[i1])) i1 = e;
        float ex = expf(logits[i1] - logits[i0]);
        float denom = 1.f + ex;
        float p0 = 1.f / denom, p1 = ex / denom;
        int s0 = atomicAdd(&g_expcnt[i0], 1);
        g_expslots[i0 * NTOK + s0] = 2 * t;
        g_gate[2 * t] = p0;
        int s1 = atomicAdd(&g_expcnt[i1], 1);
        g_expslots[i1 * NTOK + s1] = 2 * t + 1;
        g_gate[2 * t + 1] = p1;
    }
}

// ---------------- final combine ----------------------------------------------
__global__ __launch_bounds__(256) void combine_kernel(float* __restrict__ out)
{
    int idx = blockIdx.x * 256 + threadIdx.x;
    int t = idx >> 8;
    int col = idx & 255;
    float g0 = g_gate[2 * t], g1 = g_gate[2 * t + 1];
    float4 hv = ((const float4*)g_h)[idx];
    float4 y0 = ((const float4*)g_ypair)[(size_t)(2 * t) * 256 + col];
    float4 y1 = ((const float4*)g_ypair)[(size_t)(2 * t + 1) * 256 + col];
    float4 o;
    o.x = hv.x + g0 * y0.x + g1 * y1.x;
    o.y = hv.y + g0 * y0.y + g1 * y1.y;
    o.z = hv.z + g0 * y0.z + g1 * y1.z;
    o.w = hv.w + g0 * y0.w + g1 * y1.w;
    ((float4*)out)[idx] = o;
}

// ---------------- launch -----------------------------------------------------
extern "C" void kernel_launch(void* const* d_in, const int* in_sizes, int n_in,
                              void* d_out, int out_size)
{
    const float* q     = (const float*)d_in[0];
    const float* fcos  = (const float*)d_in[3];
    const float* fsin  = (const float*)d_in[4];
    const float* att_w = (const float*)d_in[5];
    const float* ffn_w = (const float*)d_in[6];
    const float* wq    = (const float*)d_in[7];
    const float* wk    = (const float*)d_in[8];
    const float* wv    = (const float*)d_in[9];
    const float* wo    = (const float*)d_in[10];
    const float* rw    = (const float*)d_in[11];
    const float* rb    = (const float*)d_in[12];
    const float* w1    = (const float*)d_in[13];
    const float* w2    = (const float*)d_in[14];
    const float* w3    = (const float*)d_in[15];
    const int*   causal= (const int*)d_in[16];
    float* out = (float*)d_out;

    float *p_xn, *p_h;
    __half *p_w1h, *p_w3h, *p_w2h, *p_xnh;
    __half *p_wqh, *p_wkh, *p_wvh, *p_woh;
    __half *p_qhh, *p_khh, *p_vhh, *p_atth;
    cudaGetSymbolAddress((void**)&p_xn, g_xn);
    cudaGetSymbolAddress((void**)&p_h, g_h);
    cudaGetSymbolAddress((void**)&p_w1h, g_w1h);
    cudaGetSymbolAddress((void**)&p_w3h, g_w3h);
    cudaGetSymbolAddress((void**)&p_w2h, g_w2h);
    cudaGetSymbolAddress((void**)&p_xnh, g_xnh);
    cudaGetSymbolAddress((void**)&p_wqh, g_wqh);
    cudaGetSymbolAddress((void**)&p_wkh, g_wkh);
    cudaGetSymbolAddress((void**)&p_wvh, g_wvh);
    cudaGetSymbolAddress((void**)&p_woh, g_woh);
    cudaGetSymbolAddress((void**)&p_qhh, g_qhh);
    cudaGetSymbolAddress((void**)&p_khh, g_khh);
    cudaGetSymbolAddress((void**)&p_vhh, g_vhh);
    cudaGetSymbolAddress((void**)&p_atth, g_atth);

    cudaFuncSetAttribute(attn_h_kernel,
                         cudaFuncAttributeMaxDynamicSharedMemorySize, ATTH_SMEM);
    cudaFuncSetAttribute(gemm_qkv_h,
                         cudaFuncAttributeMaxDynamicSharedMemorySize, PROJH_SMEM);
    cudaFuncSetAttribute(gemm_wo_h,
                         cudaFuncAttributeMaxDynamicSharedMemorySize, PROJH_SMEM);
    cudaFuncSetAttribute(moe_w13_h,
                         cudaFuncAttributeMaxDynamicSharedMemorySize, W13H_SMEM);
    cudaFuncSetAttribute(moe_w2_h,
                         cudaFuncAttributeMaxDynamicSharedMemorySize, PROJH_SMEM);

    // side stream + fork/join events (created per call; no device allocation)
    cudaStream_t s2;
    cudaStreamCreateWithFlags(&s2, cudaStreamNonBlocking);
    cudaEvent_t evFork, evJoin;
    cudaEventCreateWithFlags(&evFork, cudaEventDisableTiming);
    cudaEventCreateWithFlags(&evJoin, cudaEventDisableTiming);

    // fork: BIG expert-weight conversions run on s2, overlapping the
    // attention path (which is compute-bound, DRAM ~4%).
    cudaEventRecord(evFork, 0);
    cudaStreamWaitEvent(s2, evFork, 0);
    const int nWB = (EE * FF * DD / 4) / 1024;   // 8192 blocks
    cvt_h4c_kernel<<<nWB, 256, 0, s2>>>((const float4*)w1, (__half2*)p_w1h);
    cvt_h4c_kernel<<<nWB, 256, 0, s2>>>((const float4*)w3, (__half2*)p_w3h);
    cvt_h4c_kernel<<<nWB, 256, 0, s2>>>((const float4*)w2, (__half2*)p_w2h);
    cudaEventRecord(evJoin, s2);

    // main stream: small projection-weight conversions (needed by QKV now)
    const int nDB = (DD * DD / 4) / 1024;        // 256 blocks
    cvt_h4c_kernel<<<nDB, 256>>>((const float4*)wq, (__half2*)p_wqh);
    cvt_h4c_kernel<<<nDB, 256>>>((const float4*)wk, (__half2*)p_wkh);
    cvt_h4c_kernel<<<nDB, 256>>>((const float4*)wv, (__half2*)p_wvh);
    cvt_h4c_kernel<<<nDB, 256>>>((const float4*)wo, (__half2*)p_woh);

    // 1. qn = rmsnorm(q) -> fp16
    rmsnorm_kernel<<<NTOK, 256>>>(q, att_w, (float*)nullptr, p_xnh);

    // 2. fused QKV projection (fp16 mma, fp16 out)
    gemm_qkv_h<<<dim3(3 * DD / 128, NTOK / 128), 256, PROJH_SMEM>>>(
        p_xnh, p_qhh, p_khh, p_vhh);

    // 3. RoPE in place on fp16 q/k (q pre-scaled)
    rope_h16_kernel<<<(NTOK * HH * (HDD / 2)) / 256, 256>>>(
        p_qhh, p_khh, fcos, fsin);

    // 4. flash attention (fp16 mma) -> fp16 out
    attn_h_kernel<<<dim3(SS / 64, BB * HH), 128, ATTH_SMEM>>>(
        p_qhh, p_khh, p_vhh, p_atth, causal);

    // 5. h = q + att @ wo^T
    gemm_wo_h<<<dim3(DD / 128, NTOK / 128), 256, PROJH_SMEM>>>(
        p_atth, q, p_h);

    // 6. hn = rmsnorm(h)
    rmsnorm_kernel<<<NTOK, 256>>>(p_h, ffn_w, p_xn, p_xnh);

    // 7. routing
    zero_counts_kernel<<<1, 32>>>();
    router_kernel<<<NTOK, 256>>>(p_xn, rw, rb);

    // join: expert weights must be converted before MoE consumes them
    cudaStreamWaitEvent(0, evJoin, 0);

    // 8. MoE (fp16 mma)
    moe_w13_h<<<dim3(FF / 64, NTOK / 128, EE), 256, W13H_SMEM>>>(p_xnh);
    moe_w2_h<<<dim3(DD / 128, NTOK / 128, EE), 256, PROJH_SMEM>>>();

    // 9. combine
    combine_kernel<<<NTOK, 256>>>(out);
}

// round 17
// speedup vs baseline: 1.1234x; 1.0357x over previous
#include <cuda_runtime.h>
#include <cuda_fp16.h>
#include <math.h>
#include <stdint.h>

// Problem constants
#define BB 4
#define SS 1024
#define DD 1024
#define HH 16
#define HDD 64
#define EE 8
#define FF 4096
#define NTOK 4096      // B*S
#define NSLOT 8192     // NTOK * K(=2)
#define RMS_EPS 1e-6f
#define ATT_SCALE 0.125f   // 1/sqrt(64)

// ---------------- scratch (static device globals) ---------------------------
__device__ float g_xn[NTOK * DD];
__device__ float g_h[NTOK * DD];
__device__ float g_ypair[(size_t)NSLOT * DD];
__device__ float g_gate[NSLOT];
__device__ int   g_expcnt[EE];
__device__ int   g_expslots[EE * NTOK];
// fp16 operands
__device__ __half g_w1h[(size_t)EE * FF * DD];
__device__ __half g_w3h[(size_t)EE * FF * DD];
__device__ __half g_w2h[(size_t)EE * DD * FF];
__device__ __half g_wqh[DD * DD];
__device__ __half g_wkh[DD * DD];
__device__ __half g_wvh[DD * DD];
__device__ __half g_woh[DD * DD];
__device__ __half g_xnh[NTOK * DD];
__device__ __half g_qhh[NTOK * DD];
__device__ __half g_khh[NTOK * DD];
__device__ __half g_vhh[NTOK * DD];
__device__ __half g_atth[NTOK * DD];
__device__ __half g_hidh[(size_t)NSLOT * FF];

// ---------------- helpers ---------------------------------------------------
__device__ __forceinline__ void mma_f16(float* c, const uint32_t* a, const uint32_t* b) {
    asm volatile(
        "mma.sync.aligned.m16n8k16.row.col.f32.f16.f16.f32 "
        "{%0,%1,%2,%3}, {%4,%5,%6,%7}, {%8,%9}, {%0,%1,%2,%3};\n"
        : "+f"(c[0]), "+f"(c[1]), "+f"(c[2]), "+f"(c[3])
        : "r"(a[0]), "r"(a[1]), "r"(a[2]), "r"(a[3]), "r"(b[0]), "r"(b[1]));
}
__device__ __forceinline__ void ldsm_x4(uint32_t* r, uint32_t addr) {
    asm volatile("ldmatrix.sync.aligned.m8n8.x4.shared.b16 {%0,%1,%2,%3}, [%4];"
                 : "=r"(r[0]), "=r"(r[1]), "=r"(r[2]), "=r"(r[3]) : "r"(addr));
}

__device__ __forceinline__ void cp16(uint32_t dst, const void* src) {
    asm volatile("cp.async.cg.shared.global [%0], [%1], 16;\n"
                 :: "r"(dst), "l"(src));
}
__device__ __forceinline__ void cp16z(uint32_t dst, const void* src, int ok) {
    asm volatile("cp.async.cg.shared.global [%0], [%1], 16, %2;\n"
                 :: "r"(dst), "l"(src), "r"(ok ? 16 : 0));
}
__device__ __forceinline__ void cp_commit() {
    asm volatile("cp.async.commit_group;\n" ::: "memory");
}
template <int N>
__device__ __forceinline__ void cp_wait() {
    asm volatile("cp.async.wait_group %0;\n" :: "n"(N) : "memory");
}

// ---- fp16 smem tiles: 32-k row = 16 words, stride 20 words ------------------
#define HSTR 20
#define HA_TILE (128 * HSTR)
#define HB_TILE (64 * HSTR)
#define W13H_STAGE (HA_TILE + 2 * HB_TILE)
#define W13H_SMEM  (2 * W13H_STAGE * 4)       // 40960 B
#define PROJH_STAGE (2 * HA_TILE)
#define PROJH_SMEM  (2 * PROJH_STAGE * 4)     // 40960 B

// ---- ldmatrix lane-address setup (word offsets into the tile) ---------------
// A x4 fragment for mi: rows mbase+mi*16+(lane&15), col-words (lane>>4)*4
// B x4 fragment for an n16 block: quad=lane>>3; nblk=quad>>1; kc=(quad&1)*4
#define SETUP_LDSM_A(mtilebase)                                                \
    uint32_t aab[4];                                                           \
    {                                                                          \
        int l15 = lane & 15, l16 = (lane >> 4) * 4;                            \
        _Pragma("unroll")                                                      \
        for (int mi_ = 0; mi_ < 4; mi_++)                                      \
            aab[mi_] = (uint32_t)(((mtilebase) + mi_ * 16 + l15) * HSTR + l16);\
    }
#define BQUAD_ROW  ((lane >> 4) * 8 + (lane & 7))   /* nblk*8 + row */
#define BQUAD_KC   ((((lane >> 3) & 1)) * 4)        /* k-half col words */

// ---------------- fp32 -> fp16 conversion (coalesced, MLP=4) -----------------
__global__ __launch_bounds__(256) void cvt_h4c_kernel(
    const float4* __restrict__ src, __half2* __restrict__ dst)
{
    int base = blockIdx.x * 1024 + threadIdx.x;
    #pragma unroll
    for (int k = 0; k < 4; k++) {
        int i = base + k * 256;
        float4 v = src[i];
        dst[2 * i]     = __floats2half2_rn(v.x, v.y);
        dst[2 * i + 1] = __floats2half2_rn(v.z, v.w);
    }
}

// ---------------- RMSNorm (fp32 optional + fp16 out) -------------------------
__global__ __launch_bounds__(256) void rmsnorm_kernel(
    const float* __restrict__ x, const float* __restrict__ w,
    float* __restrict__ out, __half* __restrict__ outh)
{
    int t = blockIdx.x;
    const float4* xr = (const float4*)(x + (size_t)t * DD);
    float4 v = xr[threadIdx.x];
    float ss = v.x * v.x + v.y * v.y + v.z * v.z + v.w * v.w;
    #pragma unroll
    for (int o = 16; o; o >>= 1) ss += __shfl_xor_sync(0xffffffffu, ss, o);
    __shared__ float sh[8];
    __shared__ float stot;
    int warp = threadIdx.x >> 5;
    if ((threadIdx.x & 31) == 0) sh[warp] = ss;
    __syncthreads();
    if (threadIdx.x == 0) {
        float s = 0.f;
        #pragma unroll
        for (int i = 0; i < 8; i++) s += sh[i];
        stot = rsqrtf(s / (float)DD + RMS_EPS);
    }
    __syncthreads();
    float sc = stot;
    float4 wv = ((const float4*)w)[threadIdx.x];
    float4 o;
    o.x = v.x * sc * wv.x; o.y = v.y * sc * wv.y;
    o.z = v.z * sc * wv.z; o.w = v.w * sc * wv.w;
    if (out) ((float4*)(out + (size_t)t * DD))[threadIdx.x] = o;
    __half2* dh = (__half2*)(outh + (size_t)t * DD);
    dh[threadIdx.x * 2]     = __floats2half2_rn(o.x, o.y);
    dh[threadIdx.x * 2 + 1] = __floats2half2_rn(o.z, o.w);
}

// ---------------- fp16 GEMM fill macro ---------------------------------------
#define ISSUE_PROJH(tile, st) do {                                             \
    const int ko_ = (tile) * 32;                                               \
    const uint32_t o_ = (uint32_t)(st) * PROJH_STAGE * 4;                      \
    cp16(dA0 + o_,      Ap + ko_);                                             \
    cp16(dA0 + o_ + 16, Ap + ko_ + 8);                                         \
    cp16(dB0 + o_,      Bp + ko_);                                             \
    cp16(dB0 + o_ + 16, Bp + ko_ + 8);                                         \
    cp_commit();                                                               \
} while (0)

// ldmatrix compute for 128x128 tile (4 ni blocks = 2 B x4 loads)
// sA4/sB4 = byte addresses of stage A / B regions
#define COMPUTE_TILE_LDSM(sA4, sB4)                                            \
    _Pragma("unroll")                                                          \
    for (int s = 0; s < 2; s++) {                                              \
        int kb = s * 8;                                                        \
        uint32_t b0r[4], b1r[4];                                               \
        ldsm_x4(b0r, (sB4) + (bab0 + kb) * 4);                                 \
        ldsm_x4(b1r, (sB4) + (bab1 + kb) * 4);                                 \
        _Pragma("unroll")                                                      \
        for (int mi = 0; mi < 4; mi++) {                                       \
            uint32_t af[4];                                                    \
            ldsm_x4(af, (sA4) + (aab[mi] + kb) * 4);                           \
            mma_f16(acc[mi][0], af, b0r);                                      \
            mma_f16(acc[mi][1], af, b0r + 2);                                  \
            mma_f16(acc[mi][2], af, b1r);                                      \
            mma_f16(acc[mi][3], af, b1r + 2);                                  \
        }                                                                      \
    }

// ---------------- fused QKV projection (fp16 mma + ldmatrix) -----------------
__global__ __launch_bounds__(256) void gemm_qkv_h(
    const __half* __restrict__ A,
    __half* __restrict__ qo, __half* __restrict__ ko, __half* __restrict__ vo)
{
    extern __shared__ uint32_t smbuf[];
    const uint32_t smb = (uint32_t)__cvta_generic_to_shared(smbuf);
    const int tid = threadIdx.x;
    const int lane = tid & 31, warp = tid >> 5;
    const int warpM = warp >> 2, warpN = warp & 3;
    const int g = lane >> 2, t = lane & 3;
    const int m0 = blockIdx.y * 128;
    const int n0t = blockIdx.x * 128;

    const __half* W; __half* C; int n0;
    if (n0t < DD)            { W = g_wqh; C = qo; n0 = n0t; }
    else if (n0t < 2 * DD)   { W = g_wkh; C = ko; n0 = n0t - DD; }
    else                     { W = g_wvh; C = vo; n0 = n0t - 2 * DD; }

    float acc[4][4][4] = {};
    const int arow_f = tid >> 1;
    const int ac = (tid & 1) * 2;
    const __half* Ap = A + (size_t)(m0 + arow_f) * DD + ac * 8;
    const __half* Bp = W + (size_t)(n0 + arow_f) * DD + ac * 8;
    const uint32_t dA0 = smb + (arow_f * HSTR + ac * 4) * 4;
    const uint32_t dB0 = smb + HA_TILE * 4 + (arow_f * HSTR + ac * 4) * 4;

    SETUP_LDSM_A(warpM * 64);
    const uint32_t bab0 = (uint32_t)((warpN * 32 + BQUAD_ROW) * HSTR + BQUAD_KC);
    const uint32_t bab1 = bab0 + 16 * HSTR;

    const int nt = DD / 32;
    ISSUE_PROJH(0, 0);
    for (int kt = 0; kt < nt; kt++) {
        const int buf = kt & 1;
        if (kt + 1 < nt) { ISSUE_PROJH(kt + 1, buf ^ 1); cp_wait<1>(); }
        else             { cp_wait<0>(); }
        __syncthreads();
        const uint32_t sA4 = smb + (uint32_t)buf * PROJH_STAGE * 4;
        const uint32_t sB4 = sA4 + HA_TILE * 4;
        COMPUTE_TILE_LDSM(sA4, sB4);
        __syncthreads();
    }

    #pragma unroll
    for (int mi = 0; mi < 4; mi++) {
        int r0 = m0 + warpM * 64 + mi * 16 + g;
        #pragma unroll
        for (int ni = 0; ni < 4; ni++) {
            int c = n0 + warpN * 32 + ni * 8 + 2 * t;
            size_t i0 = (size_t)r0 * DD + c;
            size_t i1 = i0 + (size_t)8 * DD;
            *(__half2*)(C + i0) = __floats2half2_rn(acc[mi][ni][0], acc[mi][ni][1]);
            *(__half2*)(C + i1) = __floats2half2_rn(acc[mi][ni][2], acc[mi][ni][3]);
        }
    }
}

// ---------------- wo projection (fp16 mma + ldmatrix, fp32 resid) ------------
__global__ __launch_bounds__(256) void gemm_wo_h(
    const __half* __restrict__ A, const float* __restrict__ resid,
    float* __restrict__ C)
{
    extern __shared__ uint32_t smbuf[];
    const uint32_t smb = (uint32_t)__cvta_generic_to_shared(smbuf);
    const int tid = threadIdx.x;
    const int lane = tid & 31, warp = tid >> 5;
    const int warpM = warp >> 2, warpN = warp & 3;
    const int g = lane >> 2, t = lane & 3;
    const int m0 = blockIdx.y * 128, n0 = blockIdx.x * 128;

    float acc[4][4][4] = {};
    const int arow_f = tid >> 1;
    const int ac = (tid & 1) * 2;
    const __half* Ap = A + (size_t)(m0 + arow_f) * DD + ac * 8;
    const __half* Bp = g_woh + (size_t)(n0 + arow_f) * DD + ac * 8;
    const uint32_t dA0 = smb + (arow_f * HSTR + ac * 4) * 4;
    const uint32_t dB0 = smb + HA_TILE * 4 + (arow_f * HSTR + ac * 4) * 4;

    SETUP_LDSM_A(warpM * 64);
    const uint32_t bab0 = (uint32_t)((warpN * 32 + BQUAD_ROW) * HSTR + BQUAD_KC);
    const uint32_t bab1 = bab0 + 16 * HSTR;

    const int nt = DD / 32;
    ISSUE_PROJH(0, 0);
    for (int kt = 0; kt < nt; kt++) {
        const int buf = kt & 1;
        if (kt + 1 < nt) { ISSUE_PROJH(kt + 1, buf ^ 1); cp_wait<1>(); }
        else             { cp_wait<0>(); }
        __syncthreads();
        const uint32_t sA4 = smb + (uint32_t)buf * PROJH_STAGE * 4;
        const uint32_t sB4 = sA4 + HA_TILE * 4;
        COMPUTE_TILE_LDSM(sA4, sB4);
        __syncthreads();
    }

    #pragma unroll
    for (int mi = 0; mi < 4; mi++) {
        int r0 = m0 + warpM * 64 + mi * 16 + g;
        #pragma unroll
        for (int ni = 0; ni < 4; ni++) {
            int c = n0 + warpN * 32 + ni * 8 + 2 * t;
            size_t i0 = (size_t)r0 * DD + c;
            size_t i1 = i0 + (size_t)8 * DD;
            float2 r = *(const float2*)(resid + i0);
            *(float2*)(C + i0) = make_float2(acc[mi][ni][0] + r.x,
                                             acc[mi][ni][1] + r.y);
            r = *(const float2*)(resid + i1);
            *(float2*)(C + i1) = make_float2(acc[mi][ni][2] + r.x,
                                             acc[mi][ni][3] + r.y);
        }
    }
}

// ---------------- RoPE: fp16 in-place (q pre-scaled) -------------------------
__global__ void rope_h16_kernel(__half* __restrict__ qh, __half* __restrict__ kh,
                                const float* __restrict__ cosb,
                                const float* __restrict__ sinb)
{
    int idx = blockIdx.x * blockDim.x + threadIdx.x;
    int i = idx & 31;
    int th = idx >> 5;
    int t = th >> 4;
    int s = t & (SS - 1);
    float c = cosb[s * 32 + i], sn = sinb[s * 32 + i];
    size_t pi = ((size_t)th * HDD + i * 2) >> 1;
    __half2 qv = ((__half2*)qh)[pi];
    float xr = __low2float(qv), xi = __high2float(qv);
    ((__half2*)qh)[pi] = __floats2half2_rn((xr * c - xi * sn) * ATT_SCALE,
                                           (xr * sn + xi * c) * ATT_SCALE);
    __half2 kv = ((__half2*)kh)[pi];
    xr = __low2float(kv); xi = __high2float(kv);
    ((__half2*)kh)[pi] = __floats2half2_rn(xr * c - xi * sn, xr * sn + xi * c);
}

// ---------------- Flash attention (fp16 mma, fp32 softmax) -------------------
#define ASTRH 36
#define ATTH_SMEM (4 * 64 * ASTRH * 4)   // 36864 B
__global__ __launch_bounds__(128) void attn_h_kernel(
    const __half* __restrict__ Q, const __half* __restrict__ K,
    const __half* __restrict__ V, __half* __restrict__ O,
    const int* __restrict__ causal_flag)
{
    extern __shared__ uint32_t smw[];
    uint32_t* Qs = smw;
    uint32_t* Ks = Qs + 64 * ASTRH;
    uint32_t* Vt = Ks + 64 * ASTRH;
    uint32_t* Ps = Vt + 64 * ASTRH;
    __half* Vth = (__half*)Vt;
    const int qt = blockIdx.x, bh = blockIdx.y;
    const int b = bh >> 4, h = bh & 15;
    const int tid = threadIdx.x;
    const int warp = tid >> 5, lane = tid & 31;
    const int g = lane >> 2, t = lane & 3;
    const int causal = *causal_flag;
    const size_t base = (size_t)b * SS * DD + (size_t)h * HDD;
    const __half* Qb = Q + base;
    const __half* Kb = K + base;
    const __half* Vb = V + base;
    const int q0 = qt * 64;

    {
        int row = tid >> 1;
        int cw = (tid & 1) * 16;
        const uint4* src = (const uint4*)(Qb + (size_t)(q0 + row) * DD + cw * 2);
        #pragma unroll
        for (int j = 0; j < 4; j++)
            *(uint4*)&Qs[row * ASTRH + cw + j * 4] = src[j];
    }

    float m_run0 = -1e30f, m_run1 = -1e30f;
    float l_run0 = 0.f, l_run1 = 0.f;
    float Oacc[8][4] = {};
    const int mrow = warp * 16 + g;

    const int ktmax = causal ? qt : (SS / 64 - 1);
    for (int kt = 0; kt <= ktmax; kt++) {
        __syncthreads();
        {
            int row = tid >> 1;
            int cw = (tid & 1) * 16;
            const uint4* ks = (const uint4*)(Kb + (size_t)(kt * 64 + row) * DD + cw * 2);
            #pragma unroll
            for (int j = 0; j < 4; j++)
                *(uint4*)&Ks[row * ASTRH + cw + j * 4] = ks[j];
            const __half2* vs = (const __half2*)(Vb + (size_t)(kt * 64 + row) * DD + cw * 2);
            #pragma unroll
            for (int j = 0; j < 16; j++) {
                __half2 p = vs[j];
                int c = cw * 2 + j * 2;
                Vth[(c + 0) * (ASTRH * 2) + row] = __low2half(p);
                Vth[(c + 1) * (ASTRH * 2) + row] = __high2half(p);
            }
        }
        __syncthreads();

        float sacc[8][4] = {};
        #pragma unroll
        for (int s = 0; s < 4; s++) {
            int kb = s * 8;
            uint32_t af[4];
            af[0] = Qs[mrow * ASTRH + kb + t];
            af[1] = Qs[(mrow + 8) * ASTRH + kb + t];
            af[2] = Qs[mrow * ASTRH + kb + t + 4];
            af[3] = Qs[(mrow + 8) * ASTRH + kb + t + 4];
            #pragma unroll
            for (int ni = 0; ni < 8; ni++) {
                uint32_t bf[2];
                bf[0] = Ks[(ni * 8 + g) * ASTRH + kb + t];
                bf[1] = Ks[(ni * 8 + g) * ASTRH + kb + t + 4];
                mma_f16(sacc[ni], af, bf);
            }
        }

        const int row0 = q0 + mrow, row1 = row0 + 8;
        if (causal && kt == qt) {
            #pragma unroll
            for (int ni = 0; ni < 8; ni++) {
                int c0 = kt * 64 + ni * 8 + 2 * t;
                if (c0     > row0) sacc[ni][0] = -1e30f;
                if (c0 + 1 > row0) sacc[ni][1] = -1e30f;
                if (c0     > row1) sacc[ni][2] = -1e30f;
                if (c0 + 1 > row1) sacc[ni][3] = -1e30f;
            }
        }

        float ml0 = -1e30f, ml1 = -1e30f;
        #pragma unroll
        for (int ni = 0; ni < 8; ni++) {
            ml0 = fmaxf(ml0, fmaxf(sacc[ni][0], sacc[ni][1]));
            ml1 = fmaxf(ml1, fmaxf(sacc[ni][2], sacc[ni][3]));
        }
        ml0 = fmaxf(ml0, __shfl_xor_sync(0xffffffffu, ml0, 1));
        ml0 = fmaxf(ml0, __shfl_xor_sync(0xffffffffu, ml0, 2));
        ml1 = fmaxf(ml1, __shfl_xor_sync(0xffffffffu, ml1, 1));
        ml1 = fmaxf(ml1, __shfl_xor_sync(0xffffffffu, ml1, 2));
        float mn0 = fmaxf(m_run0, ml0), mn1 = fmaxf(m_run1, ml1);
        float a0 = expf(m_run0 - mn0), a1 = expf(m_run1 - mn1);
        float ps0 = 0.f, ps1 = 0.f;
        #pragma unroll
        for (int ni = 0; ni < 8; ni++) {
            float p0 = expf(sacc[ni][0] - mn0);
            float p1 = expf(sacc[ni][1] - mn0);
            float p2 = expf(sacc[ni][2] - mn1);
            float p3 = expf(sacc[ni][3] - mn1);
            ps0 += p0 + p1; ps1 += p2 + p3;
            __half2 hp0 = __floats2half2_rn(p0, p1);
            __half2 hp1 = __floats2half2_rn(p2, p3);
            Ps[mrow * ASTRH + ni * 4 + t]       = *(uint32_t*)&hp0;
            Ps[(mrow + 8) * ASTRH + ni * 4 + t] = *(uint32_t*)&hp1;
        }
        ps0 += __shfl_xor_sync(0xffffffffu, ps0, 1);
        ps0 += __shfl_xor_sync(0xffffffffu, ps0, 2);
        ps1 += __shfl_xor_sync(0xffffffffu, ps1, 1);
        ps1 += __shfl_xor_sync(0xffffffffu, ps1, 2);
        l_run0 = l_run0 * a0 + ps0;
        l_run1 = l_run1 * a1 + ps1;
        m_run0 = mn0; m_run1 = mn1;
        #pragma unroll
        for (int ni = 0; ni < 8; ni++) {
            Oacc[ni][0] *= a0; Oacc[ni][1] *= a0;
            Oacc[ni][2] *= a1; Oacc[ni][3] *= a1;
        }
        __syncwarp();

        #pragma unroll
        for (int s = 0; s < 4; s++) {
            int kb = s * 8;
            uint32_t af[4];
            af[0] = Ps[mrow * ASTRH + kb + t];
            af[1] = Ps[(mrow + 8) * ASTRH + kb + t];
            af[2] = Ps[mrow * ASTRH + kb + t + 4];
            af[3] = Ps[(mrow + 8) * ASTRH + kb + t + 4];
            #pragma unroll
            for (int ni = 0; ni < 8; ni++) {
                uint32_t bf[2];
                bf[0] = Vt[(ni * 8 + g) * ASTRH + kb + t];
                bf[1] = Vt[(ni * 8 + g) * ASTRH + kb + t + 4];
                mma_f16(Oacc[ni], af, bf);
            }
        }
    }

    float i0 = 1.f / l_run0, i1 = 1.f / l_run1;
    const int row0 = q0 + mrow;
    __half* dst0 = O + (size_t)(b * SS + row0) * DD + (size_t)h * HDD;
    __half* dst1 = dst0 + (size_t)8 * DD;
    #pragma unroll
    for (int ni = 0; ni < 8; ni++) {
        int d = ni * 8 + 2 * t;
        *(__half2*)(dst0 + d) = __floats2half2_rn(Oacc[ni][0] * i0, Oacc[ni][1] * i0);
        *(__half2*)(dst1 + d) = __floats2half2_rn(Oacc[ni][2] * i1, Oacc[ni][3] * i1);
    }
}

// ---------------- fused w1+w3 expert GEMM (fp16 mma + ldmatrix) --------------
__global__ __launch_bounds__(256) void moe_w13_h(const __half* __restrict__ A)
{
    const int e = blockIdx.z;
    const int count = g_expcnt[e];
    const int m0 = blockIdx.y * 128;
    if (m0 >= count) return;

    extern __shared__ uint32_t smbuf[];
    __shared__ int srow[128];
    const uint32_t smb = (uint32_t)__cvta_generic_to_shared(smbuf);

    const int tid = threadIdx.x;
    if (tid < 128) {
        int r = m0 + tid;
        srow[tid] = (r < count) ? g_expslots[e * NTOK + r] : -1;
    }
    __syncthreads();

    const int lane = tid & 31, warp = tid >> 5;
    const int warpM = warp >> 2, warpN = warp & 3;
    const int g = lane >> 2, t = lane & 3;
    const int n0 = blockIdx.x * 64;
    float acc1[4][2][4] = {};
    float acc3[4][2][4] = {};

    const int arow_f = tid >> 1;
    const int ac = (tid & 1) * 2;
    const int s_a = srow[arow_f];
    const int aok = (s_a >= 0);
    const __half* aptr = A + (size_t)(aok ? (s_a >> 1) : 0) * DD + ac * 8;
    const int brow = (tid & 127) >> 1;
    const int bc = (tid & 1) * 2;
    const __half* bptr = ((tid < 128) ? g_w1h : g_w3h)
                         + (size_t)e * FF * DD + (size_t)(n0 + brow) * DD + bc * 8;
    const uint32_t bRegion = (tid < 128) ? (HA_TILE * 4) : ((HA_TILE + HB_TILE) * 4);
    const uint32_t dA0 = smb + (arow_f * HSTR + ac * 4) * 4;
    const uint32_t dB0 = smb + bRegion + (brow * HSTR + bc * 4) * 4;

    SETUP_LDSM_A(warpM * 64);
    // single B x4 covers both ni (n16 block at warpN*16)
    const uint32_t babw = (uint32_t)((warpN * 16 + BQUAD_ROW) * HSTR + BQUAD_KC);

#define ISSUE_W13H(tile, st) do {                                              \
    const int ko_ = (tile) * 32;                                               \
    const uint32_t o_ = (uint32_t)(st) * W13H_STAGE * 4;                       \
    cp16z(dA0 + o_,      aptr + ko_,     aok);                                 \
    cp16z(dA0 + o_ + 16, aptr + ko_ + 8, aok);                                 \
    cp16 (dB0 + o_,      bptr + ko_);                                          \
    cp16 (dB0 + o_ + 16, bptr + ko_ + 8);                                      \
    cp_commit();                                                               \
} while (0)

    const int nt = DD / 32;
    ISSUE_W13H(0, 0);
    for (int kt = 0; kt < nt; kt++) {
        const int buf = kt & 1;
        if (kt + 1 < nt) { ISSUE_W13H(kt + 1, buf ^ 1); cp_wait<1>(); }
        else             { cp_wait<0>(); }
        __syncthreads();

        const uint32_t sS4  = smb + (uint32_t)buf * W13H_STAGE * 4;
        const uint32_t sA4  = sS4;
        const uint32_t sB14 = sS4 + HA_TILE * 4;
        const uint32_t sB34 = sS4 + (HA_TILE + HB_TILE) * 4;
        #pragma unroll
        for (int s = 0; s < 2; s++) {
            int kb = s * 8;
            uint32_t b1r[4], b3r[4];
            ldsm_x4(b1r, sB14 + (babw + kb) * 4);
            ldsm_x4(b3r, sB34 + (babw + kb) * 4);
            #pragma unroll
            for (int mi = 0; mi < 4; mi++) {
                uint32_t af[4];
                ldsm_x4(af, sA4 + (aab[mi] + kb) * 4);
                mma_f16(acc1[mi][0], af, b1r);
                mma_f16(acc1[mi][1], af, b1r + 2);
                mma_f16(acc3[mi][0], af, b3r);
                mma_f16(acc3[mi][1], af, b3r + 2);
            }
        }
        __syncthreads();
    }

    #pragma unroll
    for (int mi = 0; mi < 4; mi++) {
        int mloc0 = warpM * 64 + mi * 16 + g;
        #pragma unroll
        for (int half = 0; half < 2; half++) {
            int mloc = mloc0 + half * 8;
            int s = srow[mloc];
            if (s < 0) continue;
            #pragma unroll
            for (int ni = 0; ni < 2; ni++) {
                int c = n0 + warpN * 16 + ni * 8 + 2 * t;
                float h1x = acc1[mi][ni][half * 2],     h1y = acc1[mi][ni][half * 2 + 1];
                float h3x = acc3[mi][ni][half * 2],     h3y = acc3[mi][ni][half * 2 + 1];
                float ox = (h1x / (1.f + expf(-h1x))) * h3x;
                float oy = (h1y / (1.f + expf(-h1y))) * h3y;
                *(__half2*)(&g_hidh[(size_t)s * FF + c]) = __floats2half2_rn(ox, oy);
            }
        }
    }
}

// ---------------- w2 expert GEMM (fp16 mma + ldmatrix, N=128) ----------------
__global__ __launch_bounds__(256) void moe_w2_h()
{
    const int e = blockIdx.z;
    const int count = g_expcnt[e];
    const int m0 = blockIdx.y * 128;
    if (m0 >= count) return;

    extern __shared__ uint32_t smbuf[];
    __shared__ int srow[128];
    const uint32_t smb = (uint32_t)__cvta_generic_to_shared(smbuf);

    const int tid = threadIdx.x;
    if (tid < 128) {
        int r = m0 + tid;
        srow[tid] = (r < count) ? g_expslots[e * NTOK + r] : -1;
    }
    __syncthreads();

    const int lane = tid & 31, warp = tid >> 5;
    const int warpM = warp >> 2, warpN = warp & 3;
    const int g = lane >> 2, t = lane & 3;
    const int n0 = blockIdx.x * 128;
    float acc[4][4][4] = {};

    const int arow_f = tid >> 1;
    const int ac = (tid & 1) * 2;
    const int s_a = srow[arow_f];
    const int aok = (s_a >= 0);
    const __half* aptr = g_hidh + (size_t)(aok ? s_a : 0) * FF + ac * 8;
    const __half* bptr = g_w2h + (size_t)e * DD * FF
                         + (size_t)(n0 + arow_f) * FF + ac * 8;
    const uint32_t dA0 = smb + (arow_f * HSTR + ac * 4) * 4;
    const uint32_t dB0 = smb + HA_TILE * 4 + (arow_f * HSTR + ac * 4) * 4;

    SETUP_LDSM_A(warpM * 64);
    const uint32_t bab0 = (uint32_t)((warpN * 32 + BQUAD_ROW) * HSTR + BQUAD_KC);
    const uint32_t bab1 = bab0 + 16 * HSTR;

#define ISSUE_W2H(tile, st) do {                                               \
    const int ko_ = (tile) * 32;                                               \
    const uint32_t o_ = (uint32_t)(st) * PROJH_STAGE * 4;                      \
    cp16z(dA0 + o_,      aptr + ko_,     aok);                                 \
    cp16z(dA0 + o_ + 16, aptr + ko_ + 8, aok);                                 \
    cp16 (dB0 + o_,      bptr + ko_);                                          \
    cp16 (dB0 + o_ + 16, bptr + ko_ + 8);                                      \
    cp_commit();                                                               \
} while (0)

    const int nt = FF / 32;
    ISSUE_W2H(0, 0);
    for (int kt = 0; kt < nt; kt++) {
        const int buf = kt & 1;
        if (kt + 1 < nt) { ISSUE_W2H(kt + 1, buf ^ 1); cp_wait<1>(); }
        else             { cp_wait<0>(); }
        __syncthreads();

        const uint32_t sA4 = smb + (uint32_t)buf * PROJH_STAGE * 4;
        const uint32_t sB4 = sA4 + HA_TILE * 4;
        COMPUTE_TILE_LDSM(sA4, sB4);
        __syncthreads();
    }

    #pragma unroll
    for (int mi = 0; mi < 4; mi++) {
        int mloc0 = warpM * 64 + mi * 16 + g;
        #pragma unroll
        for (int half = 0; half < 2; half++) {
            int mloc = mloc0 + half * 8;
            int s = srow[mloc];
            if (s < 0) continue;
            #pragma unroll
            for (int ni = 0; ni < 4; ni++) {
                int c = n0 + warpN * 32 + ni * 8 + 2 * t;
                *(float2*)(&g_ypair[(size_t)s * DD + c]) =
                    make_float2(acc[mi][ni][half * 2], acc[mi][ni][half * 2 + 1]);
            }
        }
    }
}

// ---------------- router + top-2 ---------------------------------------------
__global__ void zero_counts_kernel()
{
    if (threadIdx.x < EE) g_expcnt[threadIdx.x] = 0;
}

__global__ __launch_bounds__(256) void router_kernel(
    const float* __restrict__ xn, const float* __restrict__ rw,
    const float* __restrict__ rb)
{
    int t = blockIdx.x;
    float4 xv = ((const float4*)(xn + (size_t)t * DD))[threadIdx.x];
    float lg[EE];
    #pragma unroll
    for (int e = 0; e < EE; e++) {
        float4 wv = ((const float4*)(rw + (size_t)e * DD))[threadIdx.x];
        lg[e] = xv.x * wv.x + xv.y * wv.y + xv.z * wv.z + xv.w * wv.w;
    }
    #pragma unroll
    for (int o = 16; o; o >>= 1)
        #pragma unroll
        for (int e = 0; e < EE; e++)
            lg[e] += __shfl_xor_sync(0xffffffffu, lg[e], o);
    __shared__ float sh[EE][8];
    int warp = threadIdx.x >> 5;
    if ((threadIdx.x & 31) == 0)
        #pragma unroll
        for (int e = 0; e < EE; e++) sh[e][warp] = lg[e];
    __syncthreads();
    if (threadIdx.x == 0) {
        float logits[EE];
        #pragma unroll
        for (int e = 0; e < EE; e++) {
            float s = rb[e];
            #pragma unroll
            for (int w = 0; w < 8; w++) s += sh[e][w];
            logits[e] = s;
        }
        int i0 = 0;
        #pragma unroll
        for (int e = 1; e < EE; e++) if (logits[e] > logits[i0]) i0 = e;
        int i1 = -1;
        #pragma unroll
        for (int e = 0; e < EE; e++)
            if (e != i0 && (i1 < 0 || logits[e] > logits[i1])) i1 = e;
        float ex = expf(logits[i1] - logits[i0]);
        float denom = 1.f + ex;
        float p0 = 1.f / denom, p1 = ex / denom;
        int s0 = atomicAdd(&g_expcnt[i0], 1);
        g_expslots[i0 * NTOK + s0] = 2 * t;
        g_gate[2 * t] = p0;
        int s1 = atomicAdd(&g_expcnt[i1], 1);
        g_expslots[i1 * NTOK + s1] = 2 * t + 1;
        g_gate[2 * t + 1] = p1;
    }
}

// ---------------- final combine ----------------------------------------------
__global__ __launch_bounds__(256) void combine_kernel(float* __restrict__ out)
{
    int idx = blockIdx.x * 256 + threadIdx.x;
    int t = idx >> 8;
    int col = idx & 255;
    float g0 = g_gate[2 * t], g1 = g_gate[2 * t + 1];
    float4 hv = ((const float4*)g_h)[idx];
    float4 y0 = ((const float4*)g_ypair)[(size_t)(2 * t) * 256 + col];
    float4 y1 = ((const float4*)g_ypair)[(size_t)(2 * t + 1) * 256 + col];
    float4 o;
    o.x = hv.x + g0 * y0.x + g1 * y1.x;
    o.y = hv.y + g0 * y0.y + g1 * y1.y;
    o.z = hv.z + g0 * y0.z + g1 * y1.z;
    o.w = hv.w + g0 * y0.w + g1 * y1.w;
    ((float4*)out)[idx] = o;
}

// ---------------- launch -----------------------------------------------------
extern "C" void kernel_launch(void* const* d_in, const int* in_sizes, int n_in,
                              void* d_out, int out_size)
{
    const float* q     = (const float*)d_in[0];
    const float* fcos  = (const float*)d_in[3];
    const float* fsin  = (const float*)d_in[4];
    const float* att_w = (const float*)d_in[5];
    const float* ffn_w = (const float*)d_in[6];
    const float* wq    = (const float*)d_in[7];
    const float* wk    = (const float*)d_in[8];
    const float* wv    = (const float*)d_in[9];
    const float* wo    = (const float*)d_in[10];
    const float* rw    = (const float*)d_in[11];
    const float* rb    = (const float*)d_in[12];
    const float* w1    = (const float*)d_in[13];
    const float* w2    = (const float*)d_in[14];
    const float* w3    = (const float*)d_in[15];
    const int*   causal= (const int*)d_in[16];
    float* out = (float*)d_out;

    float *p_xn, *p_h;
    __half *p_w1h, *p_w3h, *p_w2h, *p_xnh;
    __half *p_wqh, *p_wkh, *p_wvh, *p_woh;
    __half *p_qhh, *p_khh, *p_vhh, *p_atth;
    cudaGetSymbolAddress((void**)&p_xn, g_xn);
    cudaGetSymbolAddress((void**)&p_h, g_h);
    cudaGetSymbolAddress((void**)&p_w1h, g_w1h);
    cudaGetSymbolAddress((void**)&p_w3h, g_w3h);
    cudaGetSymbolAddress((void**)&p_w2h, g_w2h);
    cudaGetSymbolAddress((void**)&p_xnh, g_xnh);
    cudaGetSymbolAddress((void**)&p_wqh, g_wqh);
    cudaGetSymbolAddress((void**)&p_wkh, g_wkh);
    cudaGetSymbolAddress((void**)&p_wvh, g_wvh);
    cudaGetSymbolAddress((void**)&p_woh, g_woh);
    cudaGetSymbolAddress((void**)&p_qhh, g_qhh);
    cudaGetSymbolAddress((void**)&p_khh, g_khh);
    cudaGetSymbolAddress((void**)&p_vhh, g_vhh);
    cudaGetSymbolAddress((void**)&p_atth, g_atth);

    cudaFuncSetAttribute(attn_h_kernel,
                         cudaFuncAttributeMaxDynamicSharedMemorySize, ATTH_SMEM);
    cudaFuncSetAttribute(gemm_qkv_h,
                         cudaFuncAttributeMaxDynamicSharedMemorySize, PROJH_SMEM);
    cudaFuncSetAttribute(gemm_wo_h,
                         cudaFuncAttributeMaxDynamicSharedMemorySize, PROJH_SMEM);
    cudaFuncSetAttribute(moe_w13_h,
                         cudaFuncAttributeMaxDynamicSharedMemorySize, W13H_SMEM);
    cudaFuncSetAttribute(moe_w2_h,
                         cudaFuncAttributeMaxDynamicSharedMemorySize, PROJH_SMEM);

    // side stream + fork/join events (no device allocation)
    cudaStream_t s2;
    cudaStreamCreateWithFlags(&s2, cudaStreamNonBlocking);
    cudaEvent_t evFork, evJoin;
    cudaEventCreateWithFlags(&evFork, cudaEventDisableTiming);
    cudaEventCreateWithFlags(&evJoin, cudaEventDisableTiming);

    // fork: big expert-weight conversions overlap the attention path
    cudaEventRecord(evFork, 0);
    cudaStreamWaitEvent(s2, evFork, 0);
    const int nWB = (EE * FF * DD / 4) / 1024;
    cvt_h4c_kernel<<<nWB, 256, 0, s2>>>((const float4*)w1, (__half2*)p_w1h);
    cvt_h4c_kernel<<<nWB, 256, 0, s2>>>((const float4*)w3, (__half2*)p_w3h);
    cvt_h4c_kernel<<<nWB, 256, 0, s2>>>((const float4*)w2, (__half2*)p_w2h);
    cudaEventRecord(evJoin, s2);

    // main stream: small projection-weight conversions
    const int nDB = (DD * DD / 4) / 1024;
    cvt_h4c_kernel<<<nDB, 256>>>((const float4*)wq, (__half2*)p_wqh);
    cvt_h4c_kernel<<<nDB, 256>>>((const float4*)wk, (__half2*)p_wkh);
    cvt_h4c_kernel<<<nDB, 256>>>((const float4*)wv, (__half2*)p_wvh);
    cvt_h4c_kernel<<<nDB, 256>>>((const float4*)wo, (__half2*)p_woh);

    // 1. qn = rmsnorm(q) -> fp16
    rmsnorm_kernel<<<NTOK, 256>>>(q, att_w, (float*)nullptr, p_xnh);

    // 2. fused QKV projection (fp16 mma + ldmatrix)
    gemm_qkv_h<<<dim3(3 * DD / 128, NTOK / 128), 256, PROJH_SMEM>>>(
        p_xnh, p_qhh, p_khh, p_vhh);

    // 3. RoPE in place on fp16 q/k (q pre-scaled)
    rope_h16_kernel<<<(NTOK * HH * (HDD / 2)) / 256, 256>>>(
        p_qhh, p_khh, fcos, fsin);

    // 4. flash attention (fp16 mma) -> fp16 out
    attn_h_kernel<<<dim3(SS / 64, BB * HH), 128, ATTH_SMEM>>>(
        p_qhh, p_khh, p_vhh, p_atth, causal);

    // 5. h = q + att @ wo^T
    gemm_wo_h<<<dim3(DD / 128, NTOK / 128), 256, PROJH_SMEM>>>(
        p_atth, q, p_h);

    // 6. hn = rmsnorm(h)
    rmsnorm_kernel<<<NTOK, 256>>>(p_h, ffn_w, p_xn, p_xnh);

    // 7. routing
    zero_counts_kernel<<<1, 32>>>();
    router_kernel<<<NTOK, 256>>>(p_xn, rw, rb);

    // join: expert weights converted before MoE consumes them
    cudaStreamWaitEvent(0, evJoin, 0);

    // 8. MoE (fp16 mma + ldmatrix)
    moe_w13_h<<<dim3(FF / 64, NTOK / 128, EE), 256, W13H_SMEM>>>(p_xnh);
    moe_w2_h<<<dim3(DD / 128, NTOK / 128, EE), 256, PROJH_SMEM>>>();

    // 9. combine
    combine_kernel<<<NTOK, 256>>>(out);
}